// round 15
// baseline (speedup 1.0000x reference)
#include <cuda.h>
#include <cuda_runtime.h>
#include <cuda_fp16.h>
#include <math.h>
#include <stdint.h>

// Problem constants (B=32, N=256, D=2048, d=512, M=512)
#define ROWS  8192      // B*N
#define DIN   2048      // D
#define DOUT  512       // d
#define NKEYS 1024      // 2*M
#define NSEQ  256       // N
#define GT    2048      // B*64 winograd tiles
#define NPTS  6         // winograd F(4,3) points
#define NT_S  512       // score tiles

// ---------------- scratch (device globals; no allocation allowed) ----------------
__device__ __align__(1024) __half g_Uhi[NPTS * GT * DIN];
__device__ __align__(1024) signed char g_U8[(size_t)NPTS * GT * 2 * DIN];   // [row][128B chunks: hi64|lo64]
__device__ __align__(1024) __half g_Vhi[NPTS * DOUT * DIN];
__device__ __align__(1024) signed char g_V8[(size_t)NPTS * DOUT * 2 * DIN];
__device__ float g_M[(size_t)NPTS * GT * DOUT];
__device__ __align__(1024) __half g_Ehi[ROWS * DOUT];
__device__ __align__(1024) __half g_Elo[ROWS * DOUT];
__device__ __align__(1024) __half g_Khi[NKEYS * DOUT];
__device__ __align__(1024) __half g_Klo[NKEYS * DOUT];
__device__ float4 g_pm[(size_t)ROWS * 16];
__device__ int    g_pbi[(size_t)ROWS * 16];
__device__ float g_kv[NKEYS];
__device__ float g_kkn[NKEYS];
__device__ float g_w1dot[ROWS];
__device__ float g_qq[ROWS];

// ---------------- device helpers ----------------
__device__ __forceinline__ uint32_t smem_u32(const void* p) {
    uint32_t a;
    asm("{ .reg .u64 t; cvta.to.shared.u64 t, %1; cvt.u32.u64 %0, t; }" : "=r"(a) : "l"(p));
    return a;
}

#define MBARRIER_INIT(addr, cnt) \
    asm volatile("mbarrier.init.shared.b64 [%0], %1;" :: "r"((uint32_t)(addr)), "r"((uint32_t)(cnt)) : "memory")
#define MBARRIER_ARRIVE(addr) \
    asm volatile("mbarrier.arrive.shared.b64 _, [%0];" :: "r"((uint32_t)(addr)) : "memory")
#define MBARRIER_EXPECT_TX(addr, bytes) \
    asm volatile("mbarrier.arrive.expect_tx.shared.b64 _, [%0], %1;" :: "r"((uint32_t)(addr)), "r"((uint32_t)(bytes)) : "memory")
#define MBARRIER_WAIT_PARITY(addr, parity) do {                                        \
    uint32_t _m = (uint32_t)(addr); uint32_t _p = (uint32_t)(parity); uint32_t _d;     \
    asm volatile("{\n\t.reg .pred p;\n\t"                                              \
        "mbarrier.try_wait.parity.acquire.cta.shared::cta.b64 p, [%1], %2;\n\t"        \
        "selp.b32 %0, 1, 0, p;\n\t}"                                                   \
        : "=r"(_d) : "r"(_m), "r"(_p) : "memory");                                     \
    if (!_d) {                                                                         \
        asm volatile("{\n\t.reg .pred P1;\n\t"                                         \
            "WL_%=:\n\t"                                                               \
            "mbarrier.try_wait.parity.acquire.cta.shared::cta.b64 P1, [%0], %1, 0x989680;\n\t" \
            "@P1 bra.uni WD_%=;\n\t"                                                   \
            "bra.uni WL_%=;\n\t"                                                       \
            "WD_%=:\n\t}"                                                              \
            :: "r"(_m), "r"(_p) : "memory");                                           \
    }                                                                                  \
} while (0)

#define TMA_2D(smaddr, map, x, y, mbar) \
    asm volatile("cp.async.bulk.tensor.2d.shared::cta.global.tile.mbarrier::complete_tx::bytes " \
                 "[%0], [%1, {%2, %3}], [%4];" \
                 :: "r"((uint32_t)(smaddr)), "l"(map), "r"((int)(x)), "r"((int)(y)), \
                    "r"((uint32_t)(mbar)) : "memory")

#define LDMATRIX_X4(r0, r1, r2, r3, addr) \
    asm volatile("ldmatrix.sync.aligned.m8n8.x4.shared.b16 {%0,%1,%2,%3}, [%4];" \
                 : "=r"(r0), "=r"(r1), "=r"(r2), "=r"(r3) : "r"(addr))

#define MMA_F16_F32(d, a, b0v, b1v) \
    asm volatile("mma.sync.aligned.m16n8k16.row.col.f32.f16.f16.f32 " \
                 "{%0,%1,%2,%3}, {%4,%5,%6,%7}, {%8,%9}, {%0,%1,%2,%3};" \
                 : "+f"((d)[0]), "+f"((d)[1]), "+f"((d)[2]), "+f"((d)[3]) \
                 : "r"((a)[0]), "r"((a)[1]), "r"((a)[2]), "r"((a)[3]), \
                   "r"(b0v), "r"(b1v))

#define MMA_F16_F16(d, a, b0v, b1v) \
    asm volatile("mma.sync.aligned.m16n8k16.row.col.f16.f16.f16.f16 " \
                 "{%0,%1}, {%2,%3,%4,%5}, {%6,%7}, {%0,%1};" \
                 : "+r"((d)[0]), "+r"((d)[1]) \
                 : "r"((a)[0]), "r"((a)[1]), "r"((a)[2]), "r"((a)[3]), \
                   "r"(b0v), "r"(b1v))

#define MMA_S8(d, a, b0v, b1v) \
    asm volatile("mma.sync.aligned.m16n8k32.row.col.s32.s8.s8.s32 " \
                 "{%0,%1,%2,%3}, {%4,%5,%6,%7}, {%8,%9}, {%0,%1,%2,%3};" \
                 : "+r"((d)[0]), "+r"((d)[1]), "+r"((d)[2]), "+r"((d)[3]) \
                 : "r"((a)[0]), "r"((a)[1]), "r"((a)[2]), "r"((a)[3]), \
                   "r"(b0v), "r"(b1v))

__device__ __forceinline__ void split_f16(float x, uint32_t& h, uint32_t& l) {
    __half hb = __float2half_rn(x);
    float hf = __half2float(hb);
    __half lb = __float2half_rn(x - hf);
    h = (uint32_t)__half_as_ushort(hb);
    l = (uint32_t)__half_as_ushort(lb);
}

__device__ __forceinline__ void split2_f16(float x0, float x1, uint32_t& hw, uint32_t& lw) {
    uint32_t h0, l0, h1, l1;
    split_f16(x0, h0, l0);
    split_f16(x1, h1, l1);
    hw = h0 | (h1 << 16);
    lw = l0 | (l1 << 16);
}

__device__ __forceinline__ signed char q8(float x, float s) {
    int v = __float2int_rn(x * s);
    v = max(-127, min(127, v));
    return (signed char)v;
}

#define SW128(b) ((b) ^ (((b) >> 3) & 0x70))

// SMEM: full barriers [0,24), empty barriers [24,48), stages at 1024 + s*65536.
// Stage: AH fp16 16KB | A8 int8 16KB | BH fp16 16KB | B8 int8 16KB
#define STG_BASE   1024
#define STG_BYTES  65536
#define M_AH 0
#define M_A8 16384
#define M_BH 32768
#define M_B8 49152
// score stage aliases (fp16 lo tiles)
#define M_AL 16384
#define M_BL 49152
#define NSTAGE 3
#define SMEM_BYTES (STG_BASE + NSTAGE * STG_BYTES)   // 197632

// ============================================================
// Winograd F(4,3) input transform: X -> Uhi fp16 + U8 (hi/lo int8 interleaved)
// ============================================================
__global__ void wino_input_kernel(const float* __restrict__ X)
{
    const int gt = blockIdx.x;          // b*64 + t
    const int b = gt >> 6, t = gt & 63;
    const int n0 = 4 * t - 1;
#pragma unroll
    for (int cc = 0; cc < 4; cc++) {
        const int c = (threadIdx.x + cc * 256) * 2;
        float2 d[6];
#pragma unroll
        for (int i = 0; i < 6; i++) {
            const int n = n0 + i;
            d[i] = (n >= 0 && n < NSEQ)
                 ? *reinterpret_cast<const float2*>(X + ((size_t)b * NSEQ + n) * DIN + c)
                 : make_float2(0.f, 0.f);
        }
        float2 u[6];
        u[0].x =  4.f * d[0].x - 5.f * d[2].x + d[4].x;
        u[0].y =  4.f * d[0].y - 5.f * d[2].y + d[4].y;
        u[1].x = -4.f * (d[1].x + d[2].x) + d[3].x + d[4].x;
        u[1].y = -4.f * (d[1].y + d[2].y) + d[3].y + d[4].y;
        u[2].x =  4.f * d[1].x - 4.f * d[2].x - d[3].x + d[4].x;
        u[2].y =  4.f * d[1].y - 4.f * d[2].y - d[3].y + d[4].y;
        u[3].x = -2.f * d[1].x - d[2].x + 2.f * d[3].x + d[4].x;
        u[3].y = -2.f * d[1].y - d[2].y + 2.f * d[3].y + d[4].y;
        u[4].x =  2.f * d[1].x - d[2].x - 2.f * d[3].x + d[4].x;
        u[4].y =  2.f * d[1].y - d[2].y - 2.f * d[3].y + d[4].y;
        u[5].x =  4.f * d[1].x - 5.f * d[3].x + d[5].x;
        u[5].y =  4.f * d[1].y - 5.f * d[3].y + d[5].y;
        const int chunkoff = (c >> 6) * 128 + (c & 63);
#pragma unroll
        for (int p = 0; p < 6; p++) {
            const __half hx = __float2half_rn(u[p].x);
            const __half hy = __float2half_rn(u[p].y);
            const float rlx = u[p].x - __half2float(hx);
            const float rly = u[p].y - __half2float(hy);
            const size_t row = (size_t)(p * GT + gt);
            *reinterpret_cast<uint32_t*>(g_Uhi + row * DIN + c) =
                (uint32_t)__half_as_ushort(hx) | ((uint32_t)__half_as_ushort(hy) << 16);
            signed char* base = g_U8 + row * (2 * DIN) + chunkoff;
            base[0]  = q8(u[p].x, 2.f);        base[1]  = q8(u[p].y, 2.f);        // hi: s=2^1 inv of sUh=2^-1
            base[64] = q8(rlx, 4096.f);        base[65] = q8(rly, 4096.f);        // lo: sUl=2^-12
        }
    }
}

// ============================================================
// Winograd weight transform: conv_w -> Vhi fp16 + V8 int8
// ============================================================
__global__ void wino_weight_kernel(const float* __restrict__ conv_w)
{
    const int pidx = blockIdx.x * 256 + threadIdx.x;  // o*1024 + c/2
    const int o = pidx >> 10, cp = pidx & 1023;
    const int c = cp * 2;
    const size_t base = (size_t)o * (DIN * 3) + (size_t)c * 3;
    const float w0a = conv_w[base + 0], w1a = conv_w[base + 1], w2a = conv_w[base + 2];
    const float w0b = conv_w[base + 3], w1b = conv_w[base + 4], w2b = conv_w[base + 5];
    float va[6], vb[6];
    va[0] =  0.25f * w0a;                          vb[0] =  0.25f * w0b;
    va[1] = -(w0a + w1a + w2a) * (1.f / 6.f);      vb[1] = -(w0b + w1b + w2b) * (1.f / 6.f);
    va[2] = (-w0a + w1a - w2a) * (1.f / 6.f);      vb[2] = (-w0b + w1b - w2b) * (1.f / 6.f);
    va[3] =  w0a * (1.f / 24.f) + w1a * (1.f / 12.f) + w2a * (1.f / 6.f);
    vb[3] =  w0b * (1.f / 24.f) + w1b * (1.f / 12.f) + w2b * (1.f / 6.f);
    va[4] =  w0a * (1.f / 24.f) - w1a * (1.f / 12.f) + w2a * (1.f / 6.f);
    vb[4] =  w0b * (1.f / 24.f) - w1b * (1.f / 12.f) + w2b * (1.f / 6.f);
    va[5] =  w2a;                                  vb[5] =  w2b;
    const int chunkoff = (c >> 6) * 128 + (c & 63);
#pragma unroll
    for (int p = 0; p < 6; p++) {
        const __half hx = __float2half_rn(va[p]);
        const __half hy = __float2half_rn(vb[p]);
        const float rlx = va[p] - __half2float(hx);
        const float rly = vb[p] - __half2float(hy);
        const size_t row = (size_t)(p * DOUT + o);
        *reinterpret_cast<uint32_t*>(g_Vhi + row * DIN + c) =
            (uint32_t)__half_as_ushort(hx) | ((uint32_t)__half_as_ushort(hy) << 16);
        signed char* vb8 = g_V8 + row * (2 * DIN) + chunkoff;
        vb8[0]  = q8(va[p], 8192.f);       vb8[1]  = q8(vb[p], 8192.f);        // hi: sVh=2^-13
        vb8[64] = q8(rlx, 16777216.f);     vb8[65] = q8(rly, 16777216.f);      // lo: sVl=2^-24
    }
}

// ============================================================
// fused keys: convert to fp16 hi/lo + kv/kkn reductions (score path)
// ============================================================
__global__ void keys_kernel(const float* __restrict__ nor_keys,
                            const float* __restrict__ abn_keys,
                            const float* __restrict__ cls_mem_w) {
    const int j = blockIdx.x * 8 + (threadIdx.x >> 5);
    const int lane = threadIdx.x & 31;
    const float* key = (j < 512) ? (nor_keys + (size_t)j * DOUT)
                                 : (abn_keys + (size_t)(j - 512) * DOUT);
    const float* w2 = cls_mem_w + DOUT;
    float kv = 0.f, kn = 0.f;
#pragma unroll
    for (int t = 0; t < 4; t++) {
        const int c = (lane + t * 32) * 4;
        float4 k4 = *reinterpret_cast<const float4*>(key + c);
        float4 w4 = *reinterpret_cast<const float4*>(w2 + c);
        kv += k4.x * w4.x + k4.y * w4.y + k4.z * w4.z + k4.w * w4.w;
        kn += k4.x * k4.x + k4.y * k4.y + k4.z * k4.z + k4.w * k4.w;
        uint32_t hw0, lw0, hw1, lw1;
        split2_f16(k4.x, k4.y, hw0, lw0);
        split2_f16(k4.z, k4.w, hw1, lw1);
        const size_t e = (size_t)j * DOUT + c;
        *reinterpret_cast<uint2*>(g_Khi + e) = make_uint2(hw0, hw1);
        *reinterpret_cast<uint2*>(g_Klo + e) = make_uint2(lw0, lw1);
    }
#pragma unroll
    for (int o = 16; o; o >>= 1) {
        kv += __shfl_xor_sync(0xffffffffu, kv, o);
        kn += __shfl_xor_sync(0xffffffffu, kn, o);
    }
    if (lane == 0) { g_kv[j] = kv; g_kkn[j] = kn; }
}

// ============================================================
// WINO chunk: fp16 main (f32 acc) + int8 corrections (shared int32 acc)
// 8 warps as 4(M)x2(N), warp tile 32x64, chunk K=64.
// ============================================================
struct FragW { uint32_t ah[2][4]; uint32_t bh[4][4]; };

__device__ __forceinline__ void load_fragsW(uint32_t st, int ks, FragW& f,
                                            int wm, int wn, int lane)
{
    const int lrow  = lane & 15;
    const int khalf = lane >> 4;
    const uint32_t kb = ks * 32 + khalf * 16;
#pragma unroll
    for (int mf = 0; mf < 2; mf++) {
        const uint32_t ro = (uint32_t)((wm + mf * 16 + lrow) * 128) + kb;
        LDMATRIX_X4(f.ah[mf][0], f.ah[mf][1], f.ah[mf][2], f.ah[mf][3], st + M_AH + SW128(ro));
    }
#pragma unroll
    for (int nq = 0; nq < 4; nq++) {
        const uint32_t ro = (uint32_t)((wn + nq * 16 + lrow) * 128) + kb;
        LDMATRIX_X4(f.bh[nq][0], f.bh[nq][1], f.bh[nq][2], f.bh[nq][3], st + M_BH + SW128(ro));
    }
}

__device__ __forceinline__ void wino_chunk(uint32_t st,
                                           float accf[2][8][4],
                                           int   acci[2][8][4],
                                           int wm, int wn, int lane,
                                           FragW fr[2])
{
    const int lrow  = lane & 15;
    const int khalf = lane >> 4;
    // main pass, double buffered fragments
    load_fragsW(st, 0, fr[0], wm, wn, lane);
#pragma unroll
    for (int ks = 0; ks < 4; ks++) {
        if (ks < 3) load_fragsW(st, ks + 1, fr[(ks + 1) & 1], wm, wn, lane);
        const FragW& f = fr[ks & 1];
#pragma unroll
        for (int mf = 0; mf < 2; mf++)
#pragma unroll
            for (int nq = 0; nq < 4; nq++)
#pragma unroll
                for (int nh = 0; nh < 2; nh++)
                    MMA_F16_F32(accf[mf][nq * 2 + nh], f.ah[mf], f.bh[nq][nh], f.bh[nq][nh + 2]);
    }
    // int8 corrections: 2 k32-groups; passes Ul*Vh and Uh*Vl share int32 acc
#pragma unroll
    for (int g = 0; g < 2; g++) {
        const uint32_t kb = g * 32 + khalf * 16;
        uint32_t aul[2][4], auh[2][4];
#pragma unroll
        for (int mf = 0; mf < 2; mf++) {
            const uint32_t rb = (uint32_t)((wm + mf * 16 + lrow) * 128);
            LDMATRIX_X4(aul[mf][0], aul[mf][1], aul[mf][2], aul[mf][3], st + M_A8 + SW128(rb + 64 + kb));
            LDMATRIX_X4(auh[mf][0], auh[mf][1], auh[mf][2], auh[mf][3], st + M_A8 + SW128(rb + kb));
        }
        uint32_t bvh[4][4], bvl[4][4];
#pragma unroll
        for (int nq = 0; nq < 4; nq++) {
            const uint32_t rb = (uint32_t)((wn + nq * 16 + lrow) * 128);
            LDMATRIX_X4(bvh[nq][0], bvh[nq][1], bvh[nq][2], bvh[nq][3], st + M_B8 + SW128(rb + kb));
            LDMATRIX_X4(bvl[nq][0], bvl[nq][1], bvl[nq][2], bvl[nq][3], st + M_B8 + SW128(rb + 64 + kb));
        }
#pragma unroll
        for (int mf = 0; mf < 2; mf++)
#pragma unroll
            for (int nq = 0; nq < 4; nq++)
#pragma unroll
                for (int nh = 0; nh < 2; nh++) {
                    MMA_S8(acci[mf][nq * 2 + nh], aul[mf], bvh[nq][nh], bvh[nq][nh + 2]);
                    MMA_S8(acci[mf][nq * 2 + nh], auh[mf], bvl[nq][nh], bvl[nq][nh + 2]);
                }
    }
}

__device__ __forceinline__ float wino_val(const float accf[4], const int acci[4], int idx) {
    return accf[idx] + (float)acci[idx] * 2.9802322387695312e-08f;   // 2^-25
}

// ============================================================
// Winograd GEMM: grid (4,16,6), 256 thr, free-running ring
// ============================================================
__global__ void __launch_bounds__(256, 1) wino_gemm_kernel(
    const __grid_constant__ CUtensorMap mUh,
    const __grid_constant__ CUtensorMap mU8,
    const __grid_constant__ CUtensorMap mVh,
    const __grid_constant__ CUtensorMap mV8)
{
    extern __shared__ char smem[];
    const uint32_t sb = smem_u32(smem);
    const int tid  = threadIdx.x;
    const int wid  = tid >> 5;
    const int lane = tid & 31;
    const int bm = blockIdx.y * 128;
    const int bn = blockIdx.x * 128;
    const int p  = blockIdx.z;
    const int wm = (wid >> 1) * 32;
    const int wn = (wid & 1) * 64;

    float accf[2][8][4];
    int   acci[2][8][4];
#pragma unroll
    for (int i = 0; i < 2; i++)
#pragma unroll
        for (int j = 0; j < 8; j++)
#pragma unroll
            for (int c = 0; c < 4; c++) { accf[i][j][c] = 0.f; acci[i][j][c] = 0; }
    FragW fr[2];

    if (tid == 0) {
#pragma unroll
        for (int s = 0; s < NSTAGE; s++) {
            MBARRIER_INIT(sb + s * 8, 1);          // full
            MBARRIER_INIT(sb + 24 + s * 8, 256);   // empty
        }
    }
    __syncthreads();

    const int CHUNKS = DIN / 64;   // 32
    auto issue = [&](int i) {
        const int s = i % NSTAGE;
        const uint32_t st = sb + STG_BASE + s * STG_BYTES;
        const uint32_t mb = sb + s * 8;
        const int k0 = i * 64;
        MBARRIER_EXPECT_TX(mb, STG_BYTES);
        TMA_2D(st + M_AH, &mUh, k0,      p * GT + bm,   mb);
        TMA_2D(st + M_A8, &mU8, k0 * 2,  p * GT + bm,   mb);
        TMA_2D(st + M_BH, &mVh, k0,      p * DOUT + bn, mb);
        TMA_2D(st + M_B8, &mV8, k0 * 2,  p * DOUT + bn, mb);
    };
    if (tid == 0) { issue(0); issue(1); issue(2); }

    for (int i = 0; i < CHUNKS; i++) {
        const int s = i % NSTAGE;
        MBARRIER_WAIT_PARITY(sb + s * 8, (uint32_t)((i / NSTAGE) & 1));
        wino_chunk(sb + STG_BASE + s * STG_BYTES, accf, acci, wm, wn, lane, fr);
        MBARRIER_ARRIVE(sb + 24 + s * 8);
        if (tid == 0 && i + NSTAGE < CHUNKS) {
            MBARRIER_WAIT_PARITY(sb + 24 + s * 8, (uint32_t)((i / NSTAGE) & 1));
            issue(i + NSTAGE);
        }
    }

#pragma unroll
    for (int mf = 0; mf < 2; mf++) {
        const int row0 = bm + wm + mf * 16 + (lane >> 2);
#pragma unroll
        for (int nf = 0; nf < 8; nf++) {
            const int col = bn + wn + nf * 8 + (lane & 3) * 2;
#pragma unroll
            for (int h = 0; h < 2; h++) {
                const int row = row0 + h * 8;
                *reinterpret_cast<float2*>(
                    g_M + ((size_t)(p * GT) + row) * DOUT + col) =
                    make_float2(wino_val(accf[mf][nf], acci[mf][nf], 2 * h),
                                wino_val(accf[mf][nf], acci[mf][nf], 2 * h + 1));
            }
        }
    }
}

// ============================================================
// Winograd output transform + bias + relu -> E, fused rowstats
// ============================================================
__global__ void __launch_bounds__(256) wino_out_kernel(
    const float* __restrict__ bias,
    const float* __restrict__ cls_w,
    const float* __restrict__ cls_b,
    const float* __restrict__ cls_mem_w,
    float* __restrict__ E,
    float* __restrict__ p_out)
{
    const int gt = blockIdx.x;
    const int o  = threadIdx.x * 2;
    float2 m[6];
#pragma unroll
    for (int p = 0; p < 6; p++)
        m[p] = *reinterpret_cast<const float2*>(g_M + ((size_t)(p * GT) + gt) * DOUT + o);

    float ya[4], yb[4];
    ya[0] = m[0].x + m[1].x + m[2].x + m[3].x + m[4].x;
    yb[0] = m[0].y + m[1].y + m[2].y + m[3].y + m[4].y;
    ya[1] = m[1].x - m[2].x + 2.f * (m[3].x - m[4].x);
    yb[1] = m[1].y - m[2].y + 2.f * (m[3].y - m[4].y);
    ya[2] = m[1].x + m[2].x + 4.f * (m[3].x + m[4].x);
    yb[2] = m[1].y + m[2].y + 4.f * (m[3].y + m[4].y);
    ya[3] = m[1].x - m[2].x + 8.f * (m[3].x - m[4].x) + m[5].x;
    yb[3] = m[1].y - m[2].y + 8.f * (m[3].y - m[4].y) + m[5].y;

    const float2 b  = *reinterpret_cast<const float2*>(bias + o);
    const float2 w0 = *reinterpret_cast<const float2*>(cls_w + o);
    const float2 w1 = *reinterpret_cast<const float2*>(cls_mem_w + o);

    __shared__ float red[8][12];
    const int lane = threadIdx.x & 31, wrp = threadIdx.x >> 5;

    float d0[4], d1[4], qq[4];
#pragma unroll
    for (int r = 0; r < 4; r++) {
        const float v0 = fmaxf(ya[r] + b.x, 0.f);
        const float v1 = fmaxf(yb[r] + b.y, 0.f);
        const int row = 4 * gt + r;
        *reinterpret_cast<float2*>(E + (size_t)row * DOUT + o) = make_float2(v0, v1);
        uint32_t hw, lw;
        split2_f16(v0, v1, hw, lw);
        *reinterpret_cast<uint32_t*>(g_Ehi + (size_t)row * DOUT + o) = hw;
        *reinterpret_cast<uint32_t*>(g_Elo + (size_t)row * DOUT + o) = lw;
        d0[r] = v0 * w0.x + v1 * w0.y;
        d1[r] = v0 * w1.x + v1 * w1.y;
        qq[r] = v0 * v0 + v1 * v1;
    }
#pragma unroll
    for (int r = 0; r < 4; r++) {
#pragma unroll
        for (int off = 16; off; off >>= 1) {
            d0[r] += __shfl_xor_sync(0xffffffffu, d0[r], off);
            d1[r] += __shfl_xor_sync(0xffffffffu, d1[r], off);
            qq[r] += __shfl_xor_sync(0xffffffffu, qq[r], off);
        }
        if (lane == 0) {
            red[wrp][3 * r + 0] = d0[r];
            red[wrp][3 * r + 1] = d1[r];
            red[wrp][3 * r + 2] = qq[r];
        }
    }
    __syncthreads();
    if (threadIdx.x < 12) {
        float s = 0.f;
#pragma unroll
        for (int w = 0; w < 8; w++) s += red[w][threadIdx.x];
        const int r = threadIdx.x / 3, q = threadIdx.x - 3 * r;
        const int row = 4 * gt + r;
        if (q == 0)      p_out[row]   = 1.f / (1.f + __expf(-(s + cls_b[0])));
        else if (q == 1) g_w1dot[row] = s;
        else             g_qq[row]    = s;
    }
}

// ============================================================
// score path (unchanged fp16 3-pass, persistent, fused softmax partials)
// ============================================================
struct Frag {
    uint32_t ah[2][4], al[2][4];
    uint32_t bh[4][4], bl[4][4];
};

__device__ __forceinline__ void load_frags(uint32_t st, int ks, Frag& f,
                                           int wm, int wn, int lane)
{
    const int lrow  = lane & 15;
    const int khalf = lane >> 4;
    const uint32_t kb = ks * 32 + khalf * 16;
#pragma unroll
    for (int mf = 0; mf < 2; mf++) {
        const uint32_t ro = (uint32_t)((wm + mf * 16 + lrow) * 128) + kb;
        LDMATRIX_X4(f.ah[mf][0], f.ah[mf][1], f.ah[mf][2], f.ah[mf][3], st + M_AH + SW128(ro));
        LDMATRIX_X4(f.al[mf][0], f.al[mf][1], f.al[mf][2], f.al[mf][3], st + M_AL + SW128(ro));
    }
#pragma unroll
    for (int nq = 0; nq < 4; nq++) {
        const uint32_t ro = (uint32_t)((wn + nq * 16 + lrow) * 128) + kb;
        LDMATRIX_X4(f.bh[nq][0], f.bh[nq][1], f.bh[nq][2], f.bh[nq][3], st + M_BH + SW128(ro));
        LDMATRIX_X4(f.bl[nq][0], f.bl[nq][1], f.bl[nq][2], f.bl[nq][3], st + M_BL + SW128(ro));
    }
}

__device__ __forceinline__ void mma_chunk_pipe(uint32_t st,
                                               float accf[2][8][4],
                                               uint32_t acc1[2][8][2],
                                               uint32_t acc2[2][8][2],
                                               int wm, int wn, int lane,
                                               Frag fr[2])
{
    load_frags(st, 0, fr[0], wm, wn, lane);
#pragma unroll
    for (int ks = 0; ks < 4; ks++) {
        if (ks < 3) load_frags(st, ks + 1, fr[(ks + 1) & 1], wm, wn, lane);
        const Frag& f = fr[ks & 1];
#pragma unroll
        for (int mf = 0; mf < 2; mf++)
#pragma unroll
            for (int nq = 0; nq < 4; nq++)
#pragma unroll
                for (int nh = 0; nh < 2; nh++) {
                    MMA_F16_F32(accf[mf][nq * 2 + nh], f.ah[mf], f.bh[nq][nh], f.bh[nq][nh + 2]);
                    MMA_F16_F16(acc1[mf][nq * 2 + nh], f.ah[mf], f.bl[nq][nh], f.bl[nq][nh + 2]);
                    MMA_F16_F16(acc2[mf][nq * 2 + nh], f.al[mf], f.bh[nq][nh], f.bh[nq][nh + 2]);
                }
    }
}

__device__ __forceinline__ float frag_val(const float accf[4], const uint32_t acc1[2],
                                          const uint32_t acc2[2], int idx) {
    const __half2 c1 = *reinterpret_cast<const __half2*>(&acc1[idx >> 1]);
    const __half2 c2 = *reinterpret_cast<const __half2*>(&acc2[idx >> 1]);
    const float k1 = (idx & 1) ? __high2float(c1) : __low2float(c1);
    const float k2 = (idx & 1) ? __high2float(c2) : __low2float(c2);
    return accf[idx] + (k1 + k2);
}

#define RESET_ACCS \
    _Pragma("unroll") \
    for (int i = 0; i < 2; i++) \
        _Pragma("unroll") \
        for (int j = 0; j < 8; j++) { \
            _Pragma("unroll") \
            for (int c = 0; c < 4; c++) accf[i][j][c] = 0.f; \
            acc1[i][j][0] = 0u; acc1[i][j][1] = 0u; \
            acc2[i][j][0] = 0u; acc2[i][j][1] = 0u; \
        }

__global__ void __launch_bounds__(256, 1) score_mma_kernel(
    const __grid_constant__ CUtensorMap mEh,
    const __grid_constant__ CUtensorMap mEl,
    const __grid_constant__ CUtensorMap mKh,
    const __grid_constant__ CUtensorMap mKl)
{
    extern __shared__ char smem[];
    const uint32_t sb = smem_u32(smem);
    const int tid  = threadIdx.x;
    const int wid  = tid >> 5;
    const int lane = tid & 31;
    const int wm = (wid >> 1) * 32;
    const int wn = (wid & 1) * 64;
    const int bid = blockIdx.x;
    const int stride = gridDim.x;
    const int nown = (NT_S - bid + stride - 1) / stride;
    if (nown <= 0) return;
    const int total = nown * 8;

    float    accf[2][8][4];
    uint32_t acc1[2][8][2];
    uint32_t acc2[2][8][2];
    RESET_ACCS
    Frag fr[2];

    if (tid == 0) {
#pragma unroll
        for (int s = 0; s < NSTAGE; s++) {
            MBARRIER_INIT(sb + s * 8, 1);
            MBARRIER_INIT(sb + 24 + s * 8, 256);
        }
    }
    __syncthreads();

    auto issue = [&](int gq) {
        const int tile = bid + (gq >> 3) * stride;
        const int bm = (tile >> 3) * 128;
        const int bn = (tile & 7) * 128;
        const int s = gq % NSTAGE;
        const uint32_t st = sb + STG_BASE + s * STG_BYTES;
        const uint32_t mb = sb + s * 8;
        const int k0 = (gq & 7) * 64;
        MBARRIER_EXPECT_TX(mb, STG_BYTES);
        TMA_2D(st + M_AH, &mEh, k0, bm, mb);
        TMA_2D(st + M_AL, &mEl, k0, bm, mb);
        TMA_2D(st + M_BH, &mKh, k0, bn, mb);
        TMA_2D(st + M_BL, &mKl, k0, bn, mb);
    };
    if (tid == 0) {
        issue(0);
        if (total > 1) issue(1);
        if (total > 2) issue(2);
    }

    for (int gq = 0; gq < total; gq++) {
        const int s = gq % NSTAGE;
        const uint32_t par = (uint32_t)((gq / NSTAGE) & 1);
        MBARRIER_WAIT_PARITY(sb + s * 8, par);
        mma_chunk_pipe(sb + STG_BASE + s * STG_BYTES, accf, acc1, acc2, wm, wn, lane, fr);
        MBARRIER_ARRIVE(sb + 24 + s * 8);
        if (tid == 0 && gq + NSTAGE < total) {
            MBARRIER_WAIT_PARITY(sb + 24 + s * 8, par);
            issue(gq + NSTAGE);
        }
        if ((gq & 7) == 7) {
            const int tile = bid + (gq >> 3) * stride;
            const int bm = (tile >> 3) * 128;
            const int bn = (tile & 7) * 128;
            const int nblk = (bn + wn) >> 6;
#pragma unroll
            for (int mf = 0; mf < 2; mf++) {
#pragma unroll
                for (int h = 0; h < 2; h++) {
                    const int row = bm + wm + mf * 16 + (lane >> 2) + h * 8;
                    float vals[16];
                    float mt = -INFINITY, bv = -INFINITY;
                    int bi = 0;
#pragma unroll
                    for (int nf = 0; nf < 8; nf++) {
                        const int col0 = bn + wn + nf * 8 + (lane & 3) * 2;
                        const float v0 = frag_val(accf[mf][nf], acc1[mf][nf], acc2[mf][nf], 2 * h);
                        const float v1 = frag_val(accf[mf][nf], acc1[mf][nf], acc2[mf][nf], 2 * h + 1);
                        vals[2 * nf] = v0; vals[2 * nf + 1] = v1;
                        if (v0 > bv || (v0 == bv && col0 < bi)) { bv = v0; bi = col0; }
                        if (v1 > bv || (v1 == bv && col0 + 1 < bi)) { bv = v1; bi = col0 + 1; }
                        mt = fmaxf(mt, fmaxf(v0, v1));
                    }
                    float lt = 0.f, dt = 0.f;
#pragma unroll
                    for (int nf = 0; nf < 8; nf++) {
                        const int col0 = bn + wn + nf * 8 + (lane & 3) * 2;
                        const float e0 = __expf(vals[2 * nf] - mt);
                        const float e1 = __expf(vals[2 * nf + 1] - mt);
                        lt += e0 + e1;
                        dt += e0 * __ldg(&g_kv[col0]) + e1 * __ldg(&g_kv[col0 + 1]);
                    }
#pragma unroll
                    for (int off = 1; off < 4; off <<= 1) {
                        const float mo  = __shfl_xor_sync(0xffffffffu, mt, off);
                        const float lo  = __shfl_xor_sync(0xffffffffu, lt, off);
                        const float dto = __shfl_xor_sync(0xffffffffu, dt, off);
                        const float bvo = __shfl_xor_sync(0xffffffffu, bv, off);
                        const int   bio = __shfl_xor_sync(0xffffffffu, bi, off);
                        const float M  = fmaxf(mt, mo);
                        const float s1 = __expf(mt - M);
                        const float s2 = __expf(mo - M);
                        lt = lt * s1 + lo * s2;
                        dt = dt * s1 + dto * s2;
                        mt = M;
                        if (bvo > bv || (bvo == bv && bio < bi)) { bv = bvo; bi = bio; }
                    }
                    if ((lane & 3) == 0) {
                        const size_t off = (size_t)row * 16 + nblk;
                        g_pm[off]  = make_float4(mt, lt, dt, bv);
                        g_pbi[off] = bi;
                    }
                }
            }
            RESET_ACCS
        }
    }
}

// ============================================================
// final: merge 16 per-row partials -> up_score + both losses
// ============================================================
__global__ void softmax_final_kernel(const float* __restrict__ cls_mem_b,
                                     float* __restrict__ up_out,
                                     float* __restrict__ nor_out,
                                     float* __restrict__ abn_out)
{
    const int row = blockIdx.x * 256 + threadIdx.x;
    float m = -INFINITY, l = 0.f, d = 0.f;
    float bv0 = -INFINITY, bv1 = -INFINITY;
    int bi0 = 0, bi1 = 0;
#pragma unroll
    for (int b = 0; b < 16; b++) {
        const float4 p = g_pm[(size_t)row * 16 + b];
        const int  pbi = g_pbi[(size_t)row * 16 + b];
        const float M  = fmaxf(m, p.x);
        const float s1 = __expf(m - M);
        const float s2 = __expf(p.x - M);
        l = l * s1 + p.y * s2;
        d = d * s1 + p.z * s2;
        m = M;
        if (b < 8) { if (p.w > bv0 || (p.w == bv0 && pbi < bi0)) { bv0 = p.w; bi0 = pbi; } }
        else       { if (p.w > bv1 || (p.w == bv1 && pbi < bi1)) { bv1 = p.w; bi1 = pbi; } }
    }
    const float x = g_w1dot[row] + d / l + cls_mem_b[0];
    up_out[row] = 1.f / (1.f + __expf(-x));
    const float qq = g_qq[row];
    nor_out[row] = (qq - 2.f * bv0 + g_kkn[bi0]) * (1.f / 512.f);
    abn_out[row] = (qq - 2.f * bv1 + g_kkn[bi1]) * (1.f / 512.f);
}

// ============================================================
// host: tensormap construction (driver entry point via cudart; no -lcuda)
// ============================================================
typedef CUresult (*PFN_tmEnc)(CUtensorMap*, CUtensorMapDataType, cuuint32_t, void*,
                              const cuuint64_t*, const cuuint64_t*, const cuuint32_t*,
                              const cuuint32_t*, CUtensorMapInterleave, CUtensorMapSwizzle,
                              CUtensorMapL2promotion, CUtensorMapFloatOOBfill);

static void enc2d(PFN_tmEnc f, CUtensorMap* m, void* addr,
                  unsigned long long d0, unsigned long long d1,
                  unsigned long long stride_bytes)
{
    cuuint64_t dims[2]    = {(cuuint64_t)d0, (cuuint64_t)d1};
    cuuint64_t strides[1] = {(cuuint64_t)stride_bytes};
    cuuint32_t box[2]     = {64u, 128u};
    cuuint32_t es[2]      = {1u, 1u};
    f(m, CU_TENSOR_MAP_DATA_TYPE_FLOAT16, 2, addr, dims, strides, box, es,
      CU_TENSOR_MAP_INTERLEAVE_NONE, CU_TENSOR_MAP_SWIZZLE_128B,
      CU_TENSOR_MAP_L2_PROMOTION_L2_128B, CU_TENSOR_MAP_FLOAT_OOB_FILL_NONE);
}

static void enc2d_u8(PFN_tmEnc f, CUtensorMap* m, void* addr,
                     unsigned long long d0, unsigned long long d1,
                     unsigned long long stride_bytes)
{
    cuuint64_t dims[2]    = {(cuuint64_t)d0, (cuuint64_t)d1};
    cuuint64_t strides[1] = {(cuuint64_t)stride_bytes};
    cuuint32_t box[2]     = {128u, 128u};
    cuuint32_t es[2]      = {1u, 1u};
    f(m, CU_TENSOR_MAP_DATA_TYPE_UINT8, 2, addr, dims, strides, box, es,
      CU_TENSOR_MAP_INTERLEAVE_NONE, CU_TENSOR_MAP_SWIZZLE_128B,
      CU_TENSOR_MAP_L2_PROMOTION_L2_128B, CU_TENSOR_MAP_FLOAT_OOB_FILL_NONE);
}

extern "C" void kernel_launch(void* const* d_in, const int* in_sizes, int n_in,
                              void* d_out, int out_size)
{
    const float* ref_nor   = (const float*)d_in[0];
    // d_in[1] = ref_abn : dead (only feeds the discarded p_score[B:])
    const float* nor_keys  = (const float*)d_in[2];
    const float* abn_keys  = (const float*)d_in[3];
    const float* conv_w    = (const float*)d_in[4];
    const float* conv_b    = (const float*)d_in[5];
    const float* cls_w     = (const float*)d_in[6];
    const float* cls_b     = (const float*)d_in[7];
    const float* cls_mem_w = (const float*)d_in[8];
    const float* cls_mem_b = (const float*)d_in[9];

    float* out      = (float*)d_out;
    float* p_score  = out;
    float* up_score = out + ROWS;
    float* nor_loss = out + 2 * ROWS;
    float* abn_loss = out + 3 * ROWS;
    float* E        = out + 4 * ROWS;

    PFN_tmEnc enc = nullptr;
    cudaDriverEntryPointQueryResult qr;
    cudaGetDriverEntryPoint("cuTensorMapEncodeTiled", (void**)&enc,
                            cudaEnableDefault, &qr);
    void *pUh, *pU8, *pVh, *pV8, *pEh, *pEl, *pKh, *pKl;
    cudaGetSymbolAddress(&pUh, g_Uhi); cudaGetSymbolAddress(&pU8, g_U8);
    cudaGetSymbolAddress(&pVh, g_Vhi); cudaGetSymbolAddress(&pV8, g_V8);
    cudaGetSymbolAddress(&pEh, g_Ehi); cudaGetSymbolAddress(&pEl, g_Elo);
    cudaGetSymbolAddress(&pKh, g_Khi); cudaGetSymbolAddress(&pKl, g_Klo);

    CUtensorMap mUh, mU8, mVh, mV8, mEh, mEl, mKh, mKl;
    enc2d   (enc, &mUh, pUh, DIN,     NPTS * GT,   (unsigned long long)DIN * 2);
    enc2d_u8(enc, &mU8, pU8, 2 * DIN, NPTS * GT,   (unsigned long long)(2 * DIN));
    enc2d   (enc, &mVh, pVh, DIN,     NPTS * DOUT, (unsigned long long)DIN * 2);
    enc2d_u8(enc, &mV8, pV8, 2 * DIN, NPTS * DOUT, (unsigned long long)(2 * DIN));
    enc2d   (enc, &mEh, pEh, DOUT, ROWS,  (unsigned long long)DOUT * 2);
    enc2d   (enc, &mEl, pEl, DOUT, ROWS,  (unsigned long long)DOUT * 2);
    enc2d   (enc, &mKh, pKh, DOUT, NKEYS, (unsigned long long)DOUT * 2);
    enc2d   (enc, &mKl, pKl, DOUT, NKEYS, (unsigned long long)DOUT * 2);

    int nsm = 148;
    cudaDeviceGetAttribute(&nsm, cudaDevAttrMultiProcessorCount, 0);

    cudaFuncSetAttribute(wino_gemm_kernel,  cudaFuncAttributeMaxDynamicSharedMemorySize, SMEM_BYTES);
    cudaFuncSetAttribute(score_mma_kernel, cudaFuncAttributeMaxDynamicSharedMemorySize, SMEM_BYTES);

    wino_weight_kernel<<<(DOUT * DIN / 2) / 256, 256>>>(conv_w);
    wino_input_kernel<<<GT, 256>>>(ref_nor);
    keys_kernel<<<128, 256>>>(nor_keys, abn_keys, cls_mem_w);

    wino_gemm_kernel<<<dim3(4, 16, 6), 256, SMEM_BYTES>>>(mUh, mU8, mVh, mV8);
    wino_out_kernel<<<GT, 256>>>(conv_b, cls_w, cls_b, cls_mem_w, E, p_score);
    score_mma_kernel<<<nsm, 256, SMEM_BYTES>>>(mEh, mEl, mKh, mKl);
    softmax_final_kernel<<<32, 256>>>(cls_mem_b, up_score, nor_loss, abn_loss);
}

// round 16
// speedup vs baseline: 1.9164x; 1.9164x over previous
#include <cuda.h>
#include <cuda_runtime.h>
#include <cuda_fp16.h>
#include <math.h>
#include <stdint.h>

// Problem constants (B=32, N=256, D=2048, d=512, M=512)
#define ROWS  8192      // B*N
#define DIN   2048      // D
#define DOUT  512       // d
#define NKEYS 1024      // 2*M
#define NSEQ  256       // N
#define GT    2048      // B*64 winograd tiles
#define NPTS  6         // winograd F(4,3) points
#define NT_S  512       // score tiles (64 m x 8 n)

// ---------------- scratch (device globals; no allocation allowed) ----------------
__device__ __align__(1024) __half g_Uhi[NPTS * GT * DIN];
__device__ __align__(1024) __half g_Ulo[NPTS * GT * DIN];
__device__ __align__(1024) __half g_Vhi[NPTS * DOUT * DIN];
__device__ __align__(1024) __half g_Vlo[NPTS * DOUT * DIN];
__device__ float g_M[(size_t)NPTS * GT * DOUT];
__device__ __align__(1024) __half g_Ehi[ROWS * DOUT];
__device__ __align__(1024) __half g_Elo[ROWS * DOUT];
__device__ __align__(1024) __half g_Khi[NKEYS * DOUT];
__device__ __align__(1024) __half g_Klo[NKEYS * DOUT];
__device__ float4 g_pm[(size_t)ROWS * 16];   // per-row-block partials: m, l, d, blockmax
__device__ int    g_pbi[(size_t)ROWS * 16];  // per-row-block argmax index
__device__ float g_kv[NKEYS];
__device__ float g_kkn[NKEYS];
__device__ float g_w1dot[ROWS];
__device__ float g_qq[ROWS];

// ---------------- device helpers ----------------
__device__ __forceinline__ uint32_t smem_u32(const void* p) {
    uint32_t a;
    asm("{ .reg .u64 t; cvta.to.shared.u64 t, %1; cvt.u32.u64 %0, t; }" : "=r"(a) : "l"(p));
    return a;
}

#define MBARRIER_INIT(addr, cnt) \
    asm volatile("mbarrier.init.shared.b64 [%0], %1;" :: "r"((uint32_t)(addr)), "r"((uint32_t)(cnt)) : "memory")
#define MBARRIER_ARRIVE(addr) \
    asm volatile("mbarrier.arrive.shared.b64 _, [%0];" :: "r"((uint32_t)(addr)) : "memory")
#define MBARRIER_EXPECT_TX(addr, bytes) \
    asm volatile("mbarrier.arrive.expect_tx.shared.b64 _, [%0], %1;" :: "r"((uint32_t)(addr)), "r"((uint32_t)(bytes)) : "memory")
#define MBARRIER_WAIT_PARITY(addr, parity) do {                                        \
    uint32_t _m = (uint32_t)(addr); uint32_t _p = (uint32_t)(parity); uint32_t _d;     \
    asm volatile("{\n\t.reg .pred p;\n\t"                                              \
        "mbarrier.try_wait.parity.acquire.cta.shared::cta.b64 p, [%1], %2;\n\t"        \
        "selp.b32 %0, 1, 0, p;\n\t}"                                                   \
        : "=r"(_d) : "r"(_m), "r"(_p) : "memory");                                     \
    if (!_d) {                                                                         \
        asm volatile("{\n\t.reg .pred P1;\n\t"                                         \
            "WL_%=:\n\t"                                                               \
            "mbarrier.try_wait.parity.acquire.cta.shared::cta.b64 P1, [%0], %1, 0x989680;\n\t" \
            "@P1 bra.uni WD_%=;\n\t"                                                   \
            "bra.uni WL_%=;\n\t"                                                       \
            "WD_%=:\n\t}"                                                              \
            :: "r"(_m), "r"(_p) : "memory");                                           \
    }                                                                                  \
} while (0)

#define TMA_2D(smaddr, map, x, y, mbar) \
    asm volatile("cp.async.bulk.tensor.2d.shared::cta.global.tile.mbarrier::complete_tx::bytes " \
                 "[%0], [%1, {%2, %3}], [%4];" \
                 :: "r"((uint32_t)(smaddr)), "l"(map), "r"((int)(x)), "r"((int)(y)), \
                    "r"((uint32_t)(mbar)) : "memory")

#define LDMATRIX_X4(r0, r1, r2, r3, addr) \
    asm volatile("ldmatrix.sync.aligned.m8n8.x4.shared.b16 {%0,%1,%2,%3}, [%4];" \
                 : "=r"(r0), "=r"(r1), "=r"(r2), "=r"(r3) : "r"(addr))

#define MMA_F16_F32(d, a, b0v, b1v) \
    asm volatile("mma.sync.aligned.m16n8k16.row.col.f32.f16.f16.f32 " \
                 "{%0,%1,%2,%3}, {%4,%5,%6,%7}, {%8,%9}, {%0,%1,%2,%3};" \
                 : "+f"((d)[0]), "+f"((d)[1]), "+f"((d)[2]), "+f"((d)[3]) \
                 : "r"((a)[0]), "r"((a)[1]), "r"((a)[2]), "r"((a)[3]), \
                   "r"(b0v), "r"(b1v))

#define MMA_F16_F16(d, a, b0v, b1v) \
    asm volatile("mma.sync.aligned.m16n8k16.row.col.f16.f16.f16.f16 " \
                 "{%0,%1}, {%2,%3,%4,%5}, {%6,%7}, {%0,%1};" \
                 : "+r"((d)[0]), "+r"((d)[1]) \
                 : "r"((a)[0]), "r"((a)[1]), "r"((a)[2]), "r"((a)[3]), \
                   "r"(b0v), "r"(b1v))

__device__ __forceinline__ void split_f16(float x, uint32_t& h, uint32_t& l) {
    __half hb = __float2half_rn(x);
    float hf = __half2float(hb);
    __half lb = __float2half_rn(x - hf);
    h = (uint32_t)__half_as_ushort(hb);
    l = (uint32_t)__half_as_ushort(lb);
}

__device__ __forceinline__ void split2_f16(float x0, float x1, uint32_t& hw, uint32_t& lw) {
    uint32_t h0, l0, h1, l1;
    split_f16(x0, h0, l0);
    split_f16(x1, h1, l1);
    hw = h0 | (h1 << 16);
    lw = l0 | (l1 << 16);
}

#define SW128(b) ((b) ^ (((b) >> 3) & 0x70))

// SMEM: full barriers [0,24), empty barriers [24,48), stages at 1024 + s*65536.
#define STG_BASE   1024
#define STG_BYTES  65536
#define M_AH 0
#define M_AL 16384
#define M_BH 32768
#define M_BL 49152
#define NSTAGE 3
#define SMEM_BYTES (STG_BASE + NSTAGE * STG_BYTES)   // 197632

// ============================================================
// Winograd F(4,3) input transform
// ============================================================
__global__ void wino_input_kernel(const float* __restrict__ X)
{
    const int gt = blockIdx.x;          // b*64 + t
    const int b = gt >> 6, t = gt & 63;
    const int n0 = 4 * t - 1;
#pragma unroll
    for (int cc = 0; cc < 4; cc++) {
        const int c = (threadIdx.x + cc * 256) * 2;
        float2 d[6];
#pragma unroll
        for (int i = 0; i < 6; i++) {
            const int n = n0 + i;
            d[i] = (n >= 0 && n < NSEQ)
                 ? *reinterpret_cast<const float2*>(X + ((size_t)b * NSEQ + n) * DIN + c)
                 : make_float2(0.f, 0.f);
        }
        float2 u[6];
        u[0].x =  4.f * d[0].x - 5.f * d[2].x + d[4].x;
        u[0].y =  4.f * d[0].y - 5.f * d[2].y + d[4].y;
        u[1].x = -4.f * (d[1].x + d[2].x) + d[3].x + d[4].x;
        u[1].y = -4.f * (d[1].y + d[2].y) + d[3].y + d[4].y;
        u[2].x =  4.f * d[1].x - 4.f * d[2].x - d[3].x + d[4].x;
        u[2].y =  4.f * d[1].y - 4.f * d[2].y - d[3].y + d[4].y;
        u[3].x = -2.f * d[1].x - d[2].x + 2.f * d[3].x + d[4].x;
        u[3].y = -2.f * d[1].y - d[2].y + 2.f * d[3].y + d[4].y;
        u[4].x =  2.f * d[1].x - d[2].x - 2.f * d[3].x + d[4].x;
        u[4].y =  2.f * d[1].y - d[2].y - 2.f * d[3].y + d[4].y;
        u[5].x =  4.f * d[1].x - 5.f * d[3].x + d[5].x;
        u[5].y =  4.f * d[1].y - 5.f * d[3].y + d[5].y;
#pragma unroll
        for (int p = 0; p < 6; p++) {
            uint32_t hw, lw;
            split2_f16(u[p].x, u[p].y, hw, lw);
            const size_t off = ((size_t)(p * GT + gt)) * DIN + c;
            *reinterpret_cast<uint32_t*>(g_Uhi + off) = hw;
            *reinterpret_cast<uint32_t*>(g_Ulo + off) = lw;
        }
    }
}

// ============================================================
// Winograd weight transform
// ============================================================
__global__ void wino_weight_kernel(const float* __restrict__ conv_w)
{
    const int pidx = blockIdx.x * 256 + threadIdx.x;  // pair index: o*1024 + c/2
    const int o = pidx >> 10, cp = pidx & 1023;
    const int c = cp * 2;
    const size_t base = (size_t)o * (DIN * 3) + (size_t)c * 3;
    const float w0a = conv_w[base + 0], w1a = conv_w[base + 1], w2a = conv_w[base + 2];
    const float w0b = conv_w[base + 3], w1b = conv_w[base + 4], w2b = conv_w[base + 5];
    float va[6], vb[6];
    va[0] =  0.25f * w0a;                          vb[0] =  0.25f * w0b;
    va[1] = -(w0a + w1a + w2a) * (1.f / 6.f);      vb[1] = -(w0b + w1b + w2b) * (1.f / 6.f);
    va[2] = (-w0a + w1a - w2a) * (1.f / 6.f);      vb[2] = (-w0b + w1b - w2b) * (1.f / 6.f);
    va[3] =  w0a * (1.f / 24.f) + w1a * (1.f / 12.f) + w2a * (1.f / 6.f);
    vb[3] =  w0b * (1.f / 24.f) + w1b * (1.f / 12.f) + w2b * (1.f / 6.f);
    va[4] =  w0a * (1.f / 24.f) - w1a * (1.f / 12.f) + w2a * (1.f / 6.f);
    vb[4] =  w0b * (1.f / 24.f) - w1b * (1.f / 12.f) + w2b * (1.f / 6.f);
    va[5] =  w2a;                                  vb[5] =  w2b;
#pragma unroll
    for (int p = 0; p < 6; p++) {
        uint32_t hw, lw;
        split2_f16(va[p], vb[p], hw, lw);
        const size_t off = ((size_t)(p * DOUT + o)) * DIN + c;
        *reinterpret_cast<uint32_t*>(g_Vhi + off) = hw;
        *reinterpret_cast<uint32_t*>(g_Vlo + off) = lw;
    }
}

// ============================================================
// fused keys: convert to fp16 hi/lo + kv/kkn reductions
// ============================================================
__global__ void keys_kernel(const float* __restrict__ nor_keys,
                            const float* __restrict__ abn_keys,
                            const float* __restrict__ cls_mem_w) {
    const int j = blockIdx.x * 8 + (threadIdx.x >> 5);
    const int lane = threadIdx.x & 31;
    const float* key = (j < 512) ? (nor_keys + (size_t)j * DOUT)
                                 : (abn_keys + (size_t)(j - 512) * DOUT);
    const float* w2 = cls_mem_w + DOUT;
    float kv = 0.f, kn = 0.f;
#pragma unroll
    for (int t = 0; t < 4; t++) {
        const int c = (lane + t * 32) * 4;
        float4 k4 = *reinterpret_cast<const float4*>(key + c);
        float4 w4 = *reinterpret_cast<const float4*>(w2 + c);
        kv += k4.x * w4.x + k4.y * w4.y + k4.z * w4.z + k4.w * w4.w;
        kn += k4.x * k4.x + k4.y * k4.y + k4.z * k4.z + k4.w * k4.w;
        uint32_t hw0, lw0, hw1, lw1;
        split2_f16(k4.x, k4.y, hw0, lw0);
        split2_f16(k4.z, k4.w, hw1, lw1);
        const size_t e = (size_t)j * DOUT + c;
        *reinterpret_cast<uint2*>(g_Khi + e) = make_uint2(hw0, hw1);
        *reinterpret_cast<uint2*>(g_Klo + e) = make_uint2(lw0, lw1);
    }
#pragma unroll
    for (int o = 16; o; o >>= 1) {
        kv += __shfl_xor_sync(0xffffffffu, kv, o);
        kn += __shfl_xor_sync(0xffffffffu, kn, o);
    }
    if (lane == 0) { g_kv[j] = kv; g_kkn[j] = kn; }
}

// ============================================================
// fragment set for one k-step (warp tile 32x64)
// ============================================================
struct Frag {
    uint32_t ah[2][4], al[2][4];
    uint32_t bh[4][4], bl[4][4];
};

__device__ __forceinline__ void load_frags(uint32_t st, int ks, Frag& f,
                                           int wm, int wn, int lane)
{
    const int lrow  = lane & 15;
    const int khalf = lane >> 4;
    const uint32_t kb = ks * 32 + khalf * 16;
#pragma unroll
    for (int mf = 0; mf < 2; mf++) {
        const uint32_t ro = (uint32_t)((wm + mf * 16 + lrow) * 128) + kb;
        LDMATRIX_X4(f.ah[mf][0], f.ah[mf][1], f.ah[mf][2], f.ah[mf][3], st + M_AH + SW128(ro));
        LDMATRIX_X4(f.al[mf][0], f.al[mf][1], f.al[mf][2], f.al[mf][3], st + M_AL + SW128(ro));
    }
#pragma unroll
    for (int nq = 0; nq < 4; nq++) {
        const uint32_t ro = (uint32_t)((wn + nq * 16 + lrow) * 128) + kb;
        LDMATRIX_X4(f.bh[nq][0], f.bh[nq][1], f.bh[nq][2], f.bh[nq][3], st + M_BH + SW128(ro));
        LDMATRIX_X4(f.bl[nq][0], f.bl[nq][1], f.bl[nq][2], f.bl[nq][3], st + M_BL + SW128(ro));
    }
}

__device__ __forceinline__ void mma_frags(const Frag& f,
                                          float accf[2][8][4],
                                          uint32_t acc1[2][8][2],
                                          uint32_t acc2[2][8][2])
{
#pragma unroll
    for (int mf = 0; mf < 2; mf++)
#pragma unroll
        for (int nq = 0; nq < 4; nq++)
#pragma unroll
            for (int nh = 0; nh < 2; nh++) {
                MMA_F16_F32(accf[mf][nq * 2 + nh], f.ah[mf], f.bh[nq][nh], f.bh[nq][nh + 2]);
                MMA_F16_F16(acc1[mf][nq * 2 + nh], f.ah[mf], f.bl[nq][nh], f.bl[nq][nh + 2]);
                MMA_F16_F16(acc2[mf][nq * 2 + nh], f.al[mf], f.bh[nq][nh], f.bh[nq][nh + 2]);
            }
}

__device__ __forceinline__ void mma_chunk_pipe(uint32_t st,
                                               float accf[2][8][4],
                                               uint32_t acc1[2][8][2],
                                               uint32_t acc2[2][8][2],
                                               int wm, int wn, int lane,
                                               Frag fr[2])
{
    load_frags(st, 0, fr[0], wm, wn, lane);
#pragma unroll
    for (int ks = 0; ks < 4; ks++) {
        if (ks < 3) load_frags(st, ks + 1, fr[(ks + 1) & 1], wm, wn, lane);
        mma_frags(fr[ks & 1], accf, acc1, acc2);
    }
}

__device__ __forceinline__ float frag_val(const float accf[4], const uint32_t acc1[2],
                                          const uint32_t acc2[2], int idx) {
    const __half2 c1 = *reinterpret_cast<const __half2*>(&acc1[idx >> 1]);
    const __half2 c2 = *reinterpret_cast<const __half2*>(&acc2[idx >> 1]);
    const float k1 = (idx & 1) ? __high2float(c1) : __low2float(c1);
    const float k2 = (idx & 1) ? __high2float(c2) : __low2float(c2);
    return accf[idx] + (k1 + k2);
}

#define DECL_ACCS \
    float    accf[2][8][4]; \
    uint32_t acc1[2][8][2]; \
    uint32_t acc2[2][8][2]; \
    RESET_ACCS

#define RESET_ACCS \
    _Pragma("unroll") \
    for (int i = 0; i < 2; i++) \
        _Pragma("unroll") \
        for (int j = 0; j < 8; j++) { \
            _Pragma("unroll") \
            for (int c = 0; c < 4; c++) accf[i][j][c] = 0.f; \
            acc1[i][j][0] = 0u; acc1[i][j][1] = 0u; \
            acc2[i][j][0] = 0u; acc2[i][j][1] = 0u; \
        }

// ============================================================
// Winograd GEMM (R12 config): grid (4,16,6), 256 thr, free-running ring
// ============================================================
__global__ void __launch_bounds__(256, 1) wino_gemm_kernel(
    const __grid_constant__ CUtensorMap mUh,
    const __grid_constant__ CUtensorMap mUl,
    const __grid_constant__ CUtensorMap mVh,
    const __grid_constant__ CUtensorMap mVl)
{
    extern __shared__ char smem[];
    const uint32_t sb = smem_u32(smem);
    const int tid  = threadIdx.x;
    const int wid  = tid >> 5;
    const int lane = tid & 31;
    const int bm = blockIdx.y * 128;
    const int bn = blockIdx.x * 128;
    const int p  = blockIdx.z;
    const int wm = (wid >> 1) * 32;
    const int wn = (wid & 1) * 64;

    DECL_ACCS
    Frag fr[2];

    if (tid == 0) {
#pragma unroll
        for (int s = 0; s < NSTAGE; s++) {
            MBARRIER_INIT(sb + s * 8, 1);          // full
            MBARRIER_INIT(sb + 24 + s * 8, 256);   // empty
        }
    }
    __syncthreads();

    const int CHUNKS = DIN / 64;   // 32
    auto issue = [&](int i) {
        const int s = i % NSTAGE;
        const uint32_t st = sb + STG_BASE + s * STG_BYTES;
        const uint32_t mb = sb + s * 8;
        const int k0 = i * 64;
        MBARRIER_EXPECT_TX(mb, STG_BYTES);
        TMA_2D(st + M_AH, &mUh, k0, p * GT + bm, mb);
        TMA_2D(st + M_AL, &mUl, k0, p * GT + bm, mb);
        TMA_2D(st + M_BH, &mVh, k0, p * DOUT + bn, mb);
        TMA_2D(st + M_BL, &mVl, k0, p * DOUT + bn, mb);
    };
    if (tid == 0) { issue(0); issue(1); issue(2); }

    for (int i = 0; i < CHUNKS; i++) {
        const int s = i % NSTAGE;
        MBARRIER_WAIT_PARITY(sb + s * 8, (uint32_t)((i / NSTAGE) & 1));
        mma_chunk_pipe(sb + STG_BASE + s * STG_BYTES, accf, acc1, acc2, wm, wn, lane, fr);
        MBARRIER_ARRIVE(sb + 24 + s * 8);
        if (tid == 0 && i + NSTAGE < CHUNKS) {
            MBARRIER_WAIT_PARITY(sb + 24 + s * 8, (uint32_t)((i / NSTAGE) & 1));
            issue(i + NSTAGE);
        }
    }

#pragma unroll
    for (int mf = 0; mf < 2; mf++) {
        const int row0 = bm + wm + mf * 16 + (lane >> 2);
#pragma unroll
        for (int nf = 0; nf < 8; nf++) {
            const int col = bn + wn + nf * 8 + (lane & 3) * 2;
#pragma unroll
            for (int h = 0; h < 2; h++) {
                const int row = row0 + h * 8;
                *reinterpret_cast<float2*>(
                    g_M + ((size_t)(p * GT) + row) * DOUT + col) =
                    make_float2(frag_val(accf[mf][nf], acc1[mf][nf], acc2[mf][nf], 2 * h),
                                frag_val(accf[mf][nf], acc1[mf][nf], acc2[mf][nf], 2 * h + 1));
            }
        }
    }
}

// ============================================================
// Winograd output transform + bias + relu -> E, fused rowstats
// ============================================================
__global__ void __launch_bounds__(256) wino_out_kernel(
    const float* __restrict__ bias,
    const float* __restrict__ cls_w,
    const float* __restrict__ cls_b,
    const float* __restrict__ cls_mem_w,
    float* __restrict__ E,
    float* __restrict__ p_out)
{
    const int gt = blockIdx.x;
    const int o  = threadIdx.x * 2;
    float2 m[6];
#pragma unroll
    for (int p = 0; p < 6; p++)
        m[p] = *reinterpret_cast<const float2*>(g_M + ((size_t)(p * GT) + gt) * DOUT + o);

    float ya[4], yb[4];
    ya[0] = m[0].x + m[1].x + m[2].x + m[3].x + m[4].x;
    yb[0] = m[0].y + m[1].y + m[2].y + m[3].y + m[4].y;
    ya[1] = m[1].x - m[2].x + 2.f * (m[3].x - m[4].x);
    yb[1] = m[1].y - m[2].y + 2.f * (m[3].y - m[4].y);
    ya[2] = m[1].x + m[2].x + 4.f * (m[3].x + m[4].x);
    yb[2] = m[1].y + m[2].y + 4.f * (m[3].y + m[4].y);
    ya[3] = m[1].x - m[2].x + 8.f * (m[3].x - m[4].x) + m[5].x;
    yb[3] = m[1].y - m[2].y + 8.f * (m[3].y - m[4].y) + m[5].y;

    const float2 b  = *reinterpret_cast<const float2*>(bias + o);
    const float2 w0 = *reinterpret_cast<const float2*>(cls_w + o);
    const float2 w1 = *reinterpret_cast<const float2*>(cls_mem_w + o);

    __shared__ float red[8][12];
    const int lane = threadIdx.x & 31, wrp = threadIdx.x >> 5;

    float d0[4], d1[4], qq[4];
#pragma unroll
    for (int r = 0; r < 4; r++) {
        const float v0 = fmaxf(ya[r] + b.x, 0.f);
        const float v1 = fmaxf(yb[r] + b.y, 0.f);
        const int row = 4 * gt + r;
        *reinterpret_cast<float2*>(E + (size_t)row * DOUT + o) = make_float2(v0, v1);
        uint32_t hw, lw;
        split2_f16(v0, v1, hw, lw);
        *reinterpret_cast<uint32_t*>(g_Ehi + (size_t)row * DOUT + o) = hw;
        *reinterpret_cast<uint32_t*>(g_Elo + (size_t)row * DOUT + o) = lw;
        d0[r] = v0 * w0.x + v1 * w0.y;
        d1[r] = v0 * w1.x + v1 * w1.y;
        qq[r] = v0 * v0 + v1 * v1;
    }
#pragma unroll
    for (int r = 0; r < 4; r++) {
#pragma unroll
        for (int off = 16; off; off >>= 1) {
            d0[r] += __shfl_xor_sync(0xffffffffu, d0[r], off);
            d1[r] += __shfl_xor_sync(0xffffffffu, d1[r], off);
            qq[r] += __shfl_xor_sync(0xffffffffu, qq[r], off);
        }
        if (lane == 0) {
            red[wrp][3 * r + 0] = d0[r];
            red[wrp][3 * r + 1] = d1[r];
            red[wrp][3 * r + 2] = qq[r];
        }
    }
    __syncthreads();
    if (threadIdx.x < 12) {
        float s = 0.f;
#pragma unroll
        for (int w = 0; w < 8; w++) s += red[w][threadIdx.x];
        const int r = threadIdx.x / 3, q = threadIdx.x - 3 * r;
        const int row = 4 * gt + r;
        if (q == 0)      p_out[row]   = 1.f / (1.f + __expf(-(s + cls_b[0])));
        else if (q == 1) g_w1dot[row] = s;
        else             g_qq[row]    = s;
    }
}

// ============================================================
// statically-persistent score GEMM + fused softmax partials.
// ============================================================
__global__ void __launch_bounds__(256, 1) score_mma_kernel(
    const __grid_constant__ CUtensorMap mEh,
    const __grid_constant__ CUtensorMap mEl,
    const __grid_constant__ CUtensorMap mKh,
    const __grid_constant__ CUtensorMap mKl)
{
    extern __shared__ char smem[];
    const uint32_t sb = smem_u32(smem);
    const int tid  = threadIdx.x;
    const int wid  = tid >> 5;
    const int lane = tid & 31;
    const int wm = (wid >> 1) * 32;
    const int wn = (wid & 1) * 64;
    const int bid = blockIdx.x;
    const int stride = gridDim.x;
    const int nown = (NT_S - bid + stride - 1) / stride;
    if (nown <= 0) return;
    const int total = nown * 8;

    DECL_ACCS
    Frag fr[2];

    if (tid == 0) {
#pragma unroll
        for (int s = 0; s < NSTAGE; s++) {
            MBARRIER_INIT(sb + s * 8, 1);
            MBARRIER_INIT(sb + 24 + s * 8, 256);
        }
    }
    __syncthreads();

    auto issue = [&](int gq) {
        const int tile = bid + (gq >> 3) * stride;
        const int bm = (tile >> 3) * 128;
        const int bn = (tile & 7) * 128;
        const int s = gq % NSTAGE;
        const uint32_t st = sb + STG_BASE + s * STG_BYTES;
        const uint32_t mb = sb + s * 8;
        const int k0 = (gq & 7) * 64;
        MBARRIER_EXPECT_TX(mb, STG_BYTES);
        TMA_2D(st + M_AH, &mEh, k0, bm, mb);
        TMA_2D(st + M_AL, &mEl, k0, bm, mb);
        TMA_2D(st + M_BH, &mKh, k0, bn, mb);
        TMA_2D(st + M_BL, &mKl, k0, bn, mb);
    };
    if (tid == 0) {
        issue(0);
        if (total > 1) issue(1);
        if (total > 2) issue(2);
    }

    for (int gq = 0; gq < total; gq++) {
        const int s = gq % NSTAGE;
        const uint32_t par = (uint32_t)((gq / NSTAGE) & 1);
        MBARRIER_WAIT_PARITY(sb + s * 8, par);
        mma_chunk_pipe(sb + STG_BASE + s * STG_BYTES, accf, acc1, acc2, wm, wn, lane, fr);
        MBARRIER_ARRIVE(sb + 24 + s * 8);
        if (tid == 0 && gq + NSTAGE < total) {
            MBARRIER_WAIT_PARITY(sb + 24 + s * 8, par);
            issue(gq + NSTAGE);
        }
        if ((gq & 7) == 7) {
            const int tile = bid + (gq >> 3) * stride;
            const int bm = (tile >> 3) * 128;
            const int bn = (tile & 7) * 128;
            const int nblk = (bn + wn) >> 6;
#pragma unroll
            for (int mf = 0; mf < 2; mf++) {
#pragma unroll
                for (int h = 0; h < 2; h++) {
                    const int row = bm + wm + mf * 16 + (lane >> 2) + h * 8;
                    float vals[16];
                    float mt = -INFINITY, bv = -INFINITY;
                    int bi = 0;
#pragma unroll
                    for (int nf = 0; nf < 8; nf++) {
                        const int col0 = bn + wn + nf * 8 + (lane & 3) * 2;
                        const float v0 = frag_val(accf[mf][nf], acc1[mf][nf], acc2[mf][nf], 2 * h);
                        const float v1 = frag_val(accf[mf][nf], acc1[mf][nf], acc2[mf][nf], 2 * h + 1);
                        vals[2 * nf] = v0; vals[2 * nf + 1] = v1;
                        if (v0 > bv || (v0 == bv && col0 < bi)) { bv = v0; bi = col0; }
                        if (v1 > bv || (v1 == bv && col0 + 1 < bi)) { bv = v1; bi = col0 + 1; }
                        mt = fmaxf(mt, fmaxf(v0, v1));
                    }
                    float lt = 0.f, dt = 0.f;
#pragma unroll
                    for (int nf = 0; nf < 8; nf++) {
                        const int col0 = bn + wn + nf * 8 + (lane & 3) * 2;
                        const float e0 = __expf(vals[2 * nf] - mt);
                        const float e1 = __expf(vals[2 * nf + 1] - mt);
                        lt += e0 + e1;
                        dt += e0 * __ldg(&g_kv[col0]) + e1 * __ldg(&g_kv[col0 + 1]);
                    }
#pragma unroll
                    for (int off = 1; off < 4; off <<= 1) {
                        const float mo  = __shfl_xor_sync(0xffffffffu, mt, off);
                        const float lo  = __shfl_xor_sync(0xffffffffu, lt, off);
                        const float dto = __shfl_xor_sync(0xffffffffu, dt, off);
                        const float bvo = __shfl_xor_sync(0xffffffffu, bv, off);
                        const int   bio = __shfl_xor_sync(0xffffffffu, bi, off);
                        const float M  = fmaxf(mt, mo);
                        const float s1 = __expf(mt - M);
                        const float s2 = __expf(mo - M);
                        lt = lt * s1 + lo * s2;
                        dt = dt * s1 + dto * s2;
                        mt = M;
                        if (bvo > bv || (bvo == bv && bio < bi)) { bv = bvo; bi = bio; }
                    }
                    if ((lane & 3) == 0) {
                        const size_t off = (size_t)row * 16 + nblk;
                        g_pm[off]  = make_float4(mt, lt, dt, bv);
                        g_pbi[off] = bi;
                    }
                }
            }
            RESET_ACCS
        }
    }
}

// ============================================================
// final: merge 16 per-row partials -> up_score + both losses
// ============================================================
__global__ void softmax_final_kernel(const float* __restrict__ cls_mem_b,
                                     float* __restrict__ up_out,
                                     float* __restrict__ nor_out,
                                     float* __restrict__ abn_out)
{
    const int row = blockIdx.x * 256 + threadIdx.x;
    float m = -INFINITY, l = 0.f, d = 0.f;
    float bv0 = -INFINITY, bv1 = -INFINITY;
    int bi0 = 0, bi1 = 0;
#pragma unroll
    for (int b = 0; b < 16; b++) {
        const float4 p = g_pm[(size_t)row * 16 + b];
        const int  pbi = g_pbi[(size_t)row * 16 + b];
        const float M  = fmaxf(m, p.x);
        const float s1 = __expf(m - M);
        const float s2 = __expf(p.x - M);
        l = l * s1 + p.y * s2;
        d = d * s1 + p.z * s2;
        m = M;
        if (b < 8) { if (p.w > bv0 || (p.w == bv0 && pbi < bi0)) { bv0 = p.w; bi0 = pbi; } }
        else       { if (p.w > bv1 || (p.w == bv1 && pbi < bi1)) { bv1 = p.w; bi1 = pbi; } }
    }
    const float x = g_w1dot[row] + d / l + cls_mem_b[0];
    up_out[row] = 1.f / (1.f + __expf(-x));
    const float qq = g_qq[row];
    nor_out[row] = (qq - 2.f * bv0 + g_kkn[bi0]) * (1.f / 512.f);
    abn_out[row] = (qq - 2.f * bv1 + g_kkn[bi1]) * (1.f / 512.f);
}

// ============================================================
// host: tensormap construction (driver entry point via cudart; no -lcuda)
// ============================================================
typedef CUresult (*PFN_tmEnc)(CUtensorMap*, CUtensorMapDataType, cuuint32_t, void*,
                              const cuuint64_t*, const cuuint64_t*, const cuuint32_t*,
                              const cuuint32_t*, CUtensorMapInterleave, CUtensorMapSwizzle,
                              CUtensorMapL2promotion, CUtensorMapFloatOOBfill);

static void enc2d(PFN_tmEnc f, CUtensorMap* m, void* addr,
                  unsigned long long d0, unsigned long long d1,
                  unsigned long long stride_bytes)
{
    cuuint64_t dims[2]    = {(cuuint64_t)d0, (cuuint64_t)d1};
    cuuint64_t strides[1] = {(cuuint64_t)stride_bytes};
    cuuint32_t box[2]     = {64u, 128u};
    cuuint32_t es[2]      = {1u, 1u};
    f(m, CU_TENSOR_MAP_DATA_TYPE_FLOAT16, 2, addr, dims, strides, box, es,
      CU_TENSOR_MAP_INTERLEAVE_NONE, CU_TENSOR_MAP_SWIZZLE_128B,
      CU_TENSOR_MAP_L2_PROMOTION_L2_128B, CU_TENSOR_MAP_FLOAT_OOB_FILL_NONE);
}

extern "C" void kernel_launch(void* const* d_in, const int* in_sizes, int n_in,
                              void* d_out, int out_size)
{
    const float* ref_nor   = (const float*)d_in[0];
    // d_in[1] = ref_abn : dead (only feeds the discarded p_score[B:])
    const float* nor_keys  = (const float*)d_in[2];
    const float* abn_keys  = (const float*)d_in[3];
    const float* conv_w    = (const float*)d_in[4];
    const float* conv_b    = (const float*)d_in[5];
    const float* cls_w     = (const float*)d_in[6];
    const float* cls_b     = (const float*)d_in[7];
    const float* cls_mem_w = (const float*)d_in[8];
    const float* cls_mem_b = (const float*)d_in[9];

    float* out      = (float*)d_out;
    float* p_score  = out;
    float* up_score = out + ROWS;
    float* nor_loss = out + 2 * ROWS;
    float* abn_loss = out + 3 * ROWS;
    float* E        = out + 4 * ROWS;

    PFN_tmEnc enc = nullptr;
    cudaDriverEntryPointQueryResult qr;
    cudaGetDriverEntryPoint("cuTensorMapEncodeTiled", (void**)&enc,
                            cudaEnableDefault, &qr);
    void *pUh, *pUl, *pVh, *pVl, *pEh, *pEl, *pKh, *pKl;
    cudaGetSymbolAddress(&pUh, g_Uhi); cudaGetSymbolAddress(&pUl, g_Ulo);
    cudaGetSymbolAddress(&pVh, g_Vhi); cudaGetSymbolAddress(&pVl, g_Vlo);
    cudaGetSymbolAddress(&pEh, g_Ehi); cudaGetSymbolAddress(&pEl, g_Elo);
    cudaGetSymbolAddress(&pKh, g_Khi); cudaGetSymbolAddress(&pKl, g_Klo);

    CUtensorMap mUh, mUl, mVh, mVl, mEh, mEl, mKh, mKl;
    enc2d(enc, &mUh, pUh, DIN,  NPTS * GT,   (unsigned long long)DIN  * 2);
    enc2d(enc, &mUl, pUl, DIN,  NPTS * GT,   (unsigned long long)DIN  * 2);
    enc2d(enc, &mVh, pVh, DIN,  NPTS * DOUT, (unsigned long long)DIN  * 2);
    enc2d(enc, &mVl, pVl, DIN,  NPTS * DOUT, (unsigned long long)DIN  * 2);
    enc2d(enc, &mEh, pEh, DOUT, ROWS,        (unsigned long long)DOUT * 2);
    enc2d(enc, &mEl, pEl, DOUT, ROWS,        (unsigned long long)DOUT * 2);
    enc2d(enc, &mKh, pKh, DOUT, NKEYS,       (unsigned long long)DOUT * 2);
    enc2d(enc, &mKl, pKl, DOUT, NKEYS,       (unsigned long long)DOUT * 2);

    int nsm = 148;
    cudaDeviceGetAttribute(&nsm, cudaDevAttrMultiProcessorCount, 0);

    cudaFuncSetAttribute(wino_gemm_kernel,  cudaFuncAttributeMaxDynamicSharedMemorySize, SMEM_BYTES);
    cudaFuncSetAttribute(score_mma_kernel, cudaFuncAttributeMaxDynamicSharedMemorySize, SMEM_BYTES);

    wino_weight_kernel<<<(DOUT * DIN / 2) / 256, 256>>>(conv_w);
    wino_input_kernel<<<GT, 256>>>(ref_nor);
    keys_kernel<<<128, 256>>>(nor_keys, abn_keys, cls_mem_w);

    wino_gemm_kernel<<<dim3(4, 16, 6), 256, SMEM_BYTES>>>(mUh, mUl, mVh, mVl);
    wino_out_kernel<<<GT, 256>>>(conv_b, cls_w, cls_b, cls_mem_w, E, p_score);
    score_mma_kernel<<<nsm, 256, SMEM_BYTES>>>(mEh, mEl, mKh, mKl);
    softmax_final_kernel<<<32, 256>>>(cls_mem_b, up_score, nor_loss, abn_loss);
}

// round 17
// speedup vs baseline: 1.9665x; 1.0261x over previous
#include <cuda.h>
#include <cuda_runtime.h>
#include <cuda_fp16.h>
#include <math.h>
#include <stdint.h>

// Problem constants (B=32, N=256, D=2048, d=512, M=512)
#define ROWS  8192      // B*N
#define DIN   2048      // D
#define DOUT  512       // d
#define NKEYS 1024      // 2*M
#define NSEQ  256       // N
#define GT    2048      // B*64 winograd tiles
#define NPTS  6         // winograd F(4,3) points
#define NT_S  512       // score tiles (64 m x 8 n)

// ---------------- scratch (device globals; no allocation allowed) ----------------
__device__ __align__(1024) __half g_Uhi[NPTS * GT * DIN];
__device__ __align__(1024) __half g_Ulo[NPTS * GT * DIN];
__device__ __align__(1024) __half g_Vhi[NPTS * DOUT * DIN];
__device__ __align__(1024) __half g_Vlo[NPTS * DOUT * DIN];
__device__ float g_M[(size_t)NPTS * GT * DOUT];
__device__ __align__(1024) __half g_Ehi[ROWS * DOUT];
__device__ __align__(1024) __half g_Elo[ROWS * DOUT];
__device__ __align__(1024) __half g_Khi[NKEYS * DOUT];
__device__ __align__(1024) __half g_Klo[NKEYS * DOUT];
__device__ float4 g_pm[(size_t)ROWS * 16];   // per-row-block partials: m, l, d, blockmax
__device__ int    g_pbi[(size_t)ROWS * 16];  // per-row-block argmax index
__device__ float g_kv[NKEYS];
__device__ float g_kkn[NKEYS];
__device__ float g_w1dot[ROWS];
__device__ float g_qq[ROWS];

// ---------------- device helpers ----------------
__device__ __forceinline__ uint32_t smem_u32(const void* p) {
    uint32_t a;
    asm("{ .reg .u64 t; cvta.to.shared.u64 t, %1; cvt.u32.u64 %0, t; }" : "=r"(a) : "l"(p));
    return a;
}

#define MBARRIER_INIT(addr, cnt) \
    asm volatile("mbarrier.init.shared.b64 [%0], %1;" :: "r"((uint32_t)(addr)), "r"((uint32_t)(cnt)) : "memory")
#define MBARRIER_ARRIVE(addr) \
    asm volatile("mbarrier.arrive.shared.b64 _, [%0];" :: "r"((uint32_t)(addr)) : "memory")
#define MBARRIER_EXPECT_TX(addr, bytes) \
    asm volatile("mbarrier.arrive.expect_tx.shared.b64 _, [%0], %1;" :: "r"((uint32_t)(addr)), "r"((uint32_t)(bytes)) : "memory")
#define MBARRIER_WAIT_PARITY(addr, parity) do {                                        \
    uint32_t _m = (uint32_t)(addr); uint32_t _p = (uint32_t)(parity); uint32_t _d;     \
    asm volatile("{\n\t.reg .pred p;\n\t"                                              \
        "mbarrier.try_wait.parity.acquire.cta.shared::cta.b64 p, [%1], %2;\n\t"        \
        "selp.b32 %0, 1, 0, p;\n\t}"                                                   \
        : "=r"(_d) : "r"(_m), "r"(_p) : "memory");                                     \
    if (!_d) {                                                                         \
        asm volatile("{\n\t.reg .pred P1;\n\t"                                         \
            "WL_%=:\n\t"                                                               \
            "mbarrier.try_wait.parity.acquire.cta.shared::cta.b64 P1, [%0], %1, 0x989680;\n\t" \
            "@P1 bra.uni WD_%=;\n\t"                                                   \
            "bra.uni WL_%=;\n\t"                                                       \
            "WD_%=:\n\t}"                                                              \
            :: "r"(_m), "r"(_p) : "memory");                                           \
    }                                                                                  \
} while (0)

#define TMA_2D(smaddr, map, x, y, mbar) \
    asm volatile("cp.async.bulk.tensor.2d.shared::cta.global.tile.mbarrier::complete_tx::bytes " \
                 "[%0], [%1, {%2, %3}], [%4];" \
                 :: "r"((uint32_t)(smaddr)), "l"(map), "r"((int)(x)), "r"((int)(y)), \
                    "r"((uint32_t)(mbar)) : "memory")

#define LDMATRIX_X4(r0, r1, r2, r3, addr) \
    asm volatile("ldmatrix.sync.aligned.m8n8.x4.shared.b16 {%0,%1,%2,%3}, [%4];" \
                 : "=r"(r0), "=r"(r1), "=r"(r2), "=r"(r3) : "r"(addr))

#define MMA_F16_F32(d, a, b0v, b1v) \
    asm volatile("mma.sync.aligned.m16n8k16.row.col.f32.f16.f16.f32 " \
                 "{%0,%1,%2,%3}, {%4,%5,%6,%7}, {%8,%9}, {%0,%1,%2,%3};" \
                 : "+f"((d)[0]), "+f"((d)[1]), "+f"((d)[2]), "+f"((d)[3]) \
                 : "r"((a)[0]), "r"((a)[1]), "r"((a)[2]), "r"((a)[3]), \
                   "r"(b0v), "r"(b1v))

#define MMA_F16_F16(d, a, b0v, b1v) \
    asm volatile("mma.sync.aligned.m16n8k16.row.col.f16.f16.f16.f16 " \
                 "{%0,%1}, {%2,%3,%4,%5}, {%6,%7}, {%0,%1};" \
                 : "+r"((d)[0]), "+r"((d)[1]) \
                 : "r"((a)[0]), "r"((a)[1]), "r"((a)[2]), "r"((a)[3]), \
                   "r"(b0v), "r"(b1v))

__device__ __forceinline__ void split_f16(float x, uint32_t& h, uint32_t& l) {
    __half hb = __float2half_rn(x);
    float hf = __half2float(hb);
    __half lb = __float2half_rn(x - hf);
    h = (uint32_t)__half_as_ushort(hb);
    l = (uint32_t)__half_as_ushort(lb);
}

__device__ __forceinline__ void split2_f16(float x0, float x1, uint32_t& hw, uint32_t& lw) {
    uint32_t h0, l0, h1, l1;
    split_f16(x0, h0, l0);
    split_f16(x1, h1, l1);
    hw = h0 | (h1 << 16);
    lw = l0 | (l1 << 16);
}

#define SW128(b) ((b) ^ (((b) >> 3) & 0x70))

// SMEM: full barriers [0,24), empty barriers [24,48), stages at 1024 + s*65536.
#define STG_BASE   1024
#define STG_BYTES  65536
#define M_AH 0
#define M_AL 16384
#define M_BH 32768
#define M_BL 49152
#define NSTAGE 3
#define SMEM_BYTES (STG_BASE + NSTAGE * STG_BYTES)   // 197632

// ============================================================
// fused prep kernel: blocks [0,GT) input transform,
// [GT, GT+2048) weight transform, [GT+2048, GT+2048+128) keys
// ============================================================
__device__ __forceinline__ void prep_input(const float* __restrict__ X, int gt)
{
    const int b = gt >> 6, t = gt & 63;
    const int n0 = 4 * t - 1;
#pragma unroll
    for (int cc = 0; cc < 4; cc++) {
        const int c = (threadIdx.x + cc * 256) * 2;
        float2 d[6];
#pragma unroll
        for (int i = 0; i < 6; i++) {
            const int n = n0 + i;
            d[i] = (n >= 0 && n < NSEQ)
                 ? *reinterpret_cast<const float2*>(X + ((size_t)b * NSEQ + n) * DIN + c)
                 : make_float2(0.f, 0.f);
        }
        float2 u[6];
        u[0].x =  4.f * d[0].x - 5.f * d[2].x + d[4].x;
        u[0].y =  4.f * d[0].y - 5.f * d[2].y + d[4].y;
        u[1].x = -4.f * (d[1].x + d[2].x) + d[3].x + d[4].x;
        u[1].y = -4.f * (d[1].y + d[2].y) + d[3].y + d[4].y;
        u[2].x =  4.f * d[1].x - 4.f * d[2].x - d[3].x + d[4].x;
        u[2].y =  4.f * d[1].y - 4.f * d[2].y - d[3].y + d[4].y;
        u[3].x = -2.f * d[1].x - d[2].x + 2.f * d[3].x + d[4].x;
        u[3].y = -2.f * d[1].y - d[2].y + 2.f * d[3].y + d[4].y;
        u[4].x =  2.f * d[1].x - d[2].x - 2.f * d[3].x + d[4].x;
        u[4].y =  2.f * d[1].y - d[2].y - 2.f * d[3].y + d[4].y;
        u[5].x =  4.f * d[1].x - 5.f * d[3].x + d[5].x;
        u[5].y =  4.f * d[1].y - 5.f * d[3].y + d[5].y;
#pragma unroll
        for (int p = 0; p < 6; p++) {
            uint32_t hw, lw;
            split2_f16(u[p].x, u[p].y, hw, lw);
            const size_t off = ((size_t)(p * GT + gt)) * DIN + c;
            *reinterpret_cast<uint32_t*>(g_Uhi + off) = hw;
            *reinterpret_cast<uint32_t*>(g_Ulo + off) = lw;
        }
    }
}

__device__ __forceinline__ void prep_weight(const float* __restrict__ conv_w, int blk)
{
    const int pidx = blk * 256 + threadIdx.x;  // pair index: o*1024 + c/2
    const int o = pidx >> 10, cp = pidx & 1023;
    const int c = cp * 2;
    const size_t base = (size_t)o * (DIN * 3) + (size_t)c * 3;
    const float w0a = conv_w[base + 0], w1a = conv_w[base + 1], w2a = conv_w[base + 2];
    const float w0b = conv_w[base + 3], w1b = conv_w[base + 4], w2b = conv_w[base + 5];
    float va[6], vb[6];
    va[0] =  0.25f * w0a;                          vb[0] =  0.25f * w0b;
    va[1] = -(w0a + w1a + w2a) * (1.f / 6.f);      vb[1] = -(w0b + w1b + w2b) * (1.f / 6.f);
    va[2] = (-w0a + w1a - w2a) * (1.f / 6.f);      vb[2] = (-w0b + w1b - w2b) * (1.f / 6.f);
    va[3] =  w0a * (1.f / 24.f) + w1a * (1.f / 12.f) + w2a * (1.f / 6.f);
    vb[3] =  w0b * (1.f / 24.f) + w1b * (1.f / 12.f) + w2b * (1.f / 6.f);
    va[4] =  w0a * (1.f / 24.f) - w1a * (1.f / 12.f) + w2a * (1.f / 6.f);
    vb[4] =  w0b * (1.f / 24.f) - w1b * (1.f / 12.f) + w2b * (1.f / 6.f);
    va[5] =  w2a;                                  vb[5] =  w2b;
#pragma unroll
    for (int p = 0; p < 6; p++) {
        uint32_t hw, lw;
        split2_f16(va[p], vb[p], hw, lw);
        const size_t off = ((size_t)(p * DOUT + o)) * DIN + c;
        *reinterpret_cast<uint32_t*>(g_Vhi + off) = hw;
        *reinterpret_cast<uint32_t*>(g_Vlo + off) = lw;
    }
}

__device__ __forceinline__ void prep_keys(const float* __restrict__ nor_keys,
                                          const float* __restrict__ abn_keys,
                                          const float* __restrict__ cls_mem_w, int blk)
{
    const int j = blk * 8 + (threadIdx.x >> 5);
    const int lane = threadIdx.x & 31;
    const float* key = (j < 512) ? (nor_keys + (size_t)j * DOUT)
                                 : (abn_keys + (size_t)(j - 512) * DOUT);
    const float* w2 = cls_mem_w + DOUT;
    float kv = 0.f, kn = 0.f;
#pragma unroll
    for (int t = 0; t < 4; t++) {
        const int c = (lane + t * 32) * 4;
        float4 k4 = *reinterpret_cast<const float4*>(key + c);
        float4 w4 = *reinterpret_cast<const float4*>(w2 + c);
        kv += k4.x * w4.x + k4.y * w4.y + k4.z * w4.z + k4.w * w4.w;
        kn += k4.x * k4.x + k4.y * k4.y + k4.z * k4.z + k4.w * k4.w;
        uint32_t hw0, lw0, hw1, lw1;
        split2_f16(k4.x, k4.y, hw0, lw0);
        split2_f16(k4.z, k4.w, hw1, lw1);
        const size_t e = (size_t)j * DOUT + c;
        *reinterpret_cast<uint2*>(g_Khi + e) = make_uint2(hw0, hw1);
        *reinterpret_cast<uint2*>(g_Klo + e) = make_uint2(lw0, lw1);
    }
#pragma unroll
    for (int o = 16; o; o >>= 1) {
        kv += __shfl_xor_sync(0xffffffffu, kv, o);
        kn += __shfl_xor_sync(0xffffffffu, kn, o);
    }
    if (lane == 0) { g_kv[j] = kv; g_kkn[j] = kn; }
}

__global__ void prep_kernel(const float* __restrict__ X,
                            const float* __restrict__ conv_w,
                            const float* __restrict__ nor_keys,
                            const float* __restrict__ abn_keys,
                            const float* __restrict__ cls_mem_w)
{
    const int b = blockIdx.x;
    if (b < GT)                 prep_input(X, b);
    else if (b < GT + 2048)     prep_weight(conv_w, b - GT);
    else                        prep_keys(nor_keys, abn_keys, cls_mem_w, b - GT - 2048);
}

// ============================================================
// fragment set for one k-step (warp tile 32x64)
// ============================================================
struct Frag {
    uint32_t ah[2][4], al[2][4];
    uint32_t bh[4][4], bl[4][4];
};

__device__ __forceinline__ void load_frags(uint32_t st, int ks, Frag& f,
                                           int wm, int wn, int lane)
{
    const int lrow  = lane & 15;
    const int khalf = lane >> 4;
    const uint32_t kb = ks * 32 + khalf * 16;
#pragma unroll
    for (int mf = 0; mf < 2; mf++) {
        const uint32_t ro = (uint32_t)((wm + mf * 16 + lrow) * 128) + kb;
        LDMATRIX_X4(f.ah[mf][0], f.ah[mf][1], f.ah[mf][2], f.ah[mf][3], st + M_AH + SW128(ro));
        LDMATRIX_X4(f.al[mf][0], f.al[mf][1], f.al[mf][2], f.al[mf][3], st + M_AL + SW128(ro));
    }
#pragma unroll
    for (int nq = 0; nq < 4; nq++) {
        const uint32_t ro = (uint32_t)((wn + nq * 16 + lrow) * 128) + kb;
        LDMATRIX_X4(f.bh[nq][0], f.bh[nq][1], f.bh[nq][2], f.bh[nq][3], st + M_BH + SW128(ro));
        LDMATRIX_X4(f.bl[nq][0], f.bl[nq][1], f.bl[nq][2], f.bl[nq][3], st + M_BL + SW128(ro));
    }
}

__device__ __forceinline__ void mma_frags(const Frag& f,
                                          float accf[2][8][4],
                                          uint32_t acc1[2][8][2],
                                          uint32_t acc2[2][8][2])
{
#pragma unroll
    for (int mf = 0; mf < 2; mf++)
#pragma unroll
        for (int nq = 0; nq < 4; nq++)
#pragma unroll
            for (int nh = 0; nh < 2; nh++) {
                MMA_F16_F32(accf[mf][nq * 2 + nh], f.ah[mf], f.bh[nq][nh], f.bh[nq][nh + 2]);
                MMA_F16_F16(acc1[mf][nq * 2 + nh], f.ah[mf], f.bl[nq][nh], f.bl[nq][nh + 2]);
                MMA_F16_F16(acc2[mf][nq * 2 + nh], f.al[mf], f.bh[nq][nh], f.bh[nq][nh + 2]);
            }
}

__device__ __forceinline__ void mma_chunk_pipe(uint32_t st,
                                               float accf[2][8][4],
                                               uint32_t acc1[2][8][2],
                                               uint32_t acc2[2][8][2],
                                               int wm, int wn, int lane,
                                               Frag fr[2])
{
    load_frags(st, 0, fr[0], wm, wn, lane);
#pragma unroll
    for (int ks = 0; ks < 4; ks++) {
        if (ks < 3) load_frags(st, ks + 1, fr[(ks + 1) & 1], wm, wn, lane);
        mma_frags(fr[ks & 1], accf, acc1, acc2);
    }
}

__device__ __forceinline__ float frag_val(const float accf[4], const uint32_t acc1[2],
                                          const uint32_t acc2[2], int idx) {
    const __half2 c1 = *reinterpret_cast<const __half2*>(&acc1[idx >> 1]);
    const __half2 c2 = *reinterpret_cast<const __half2*>(&acc2[idx >> 1]);
    const float k1 = (idx & 1) ? __high2float(c1) : __low2float(c1);
    const float k2 = (idx & 1) ? __high2float(c2) : __low2float(c2);
    return accf[idx] + (k1 + k2);
}

#define DECL_ACCS \
    float    accf[2][8][4]; \
    uint32_t acc1[2][8][2]; \
    uint32_t acc2[2][8][2]; \
    RESET_ACCS

#define RESET_ACCS \
    _Pragma("unroll") \
    for (int i = 0; i < 2; i++) \
        _Pragma("unroll") \
        for (int j = 0; j < 8; j++) { \
            _Pragma("unroll") \
            for (int c = 0; c < 4; c++) accf[i][j][c] = 0.f; \
            acc1[i][j][0] = 0u; acc1[i][j][1] = 0u; \
            acc2[i][j][0] = 0u; acc2[i][j][1] = 0u; \
        }

// ============================================================
// Winograd GEMM: grid (4,16,6), 256 thr, free-running ring
// ============================================================
__global__ void __launch_bounds__(256, 1) wino_gemm_kernel(
    const __grid_constant__ CUtensorMap mUh,
    const __grid_constant__ CUtensorMap mUl,
    const __grid_constant__ CUtensorMap mVh,
    const __grid_constant__ CUtensorMap mVl)
{
    extern __shared__ char smem[];
    const uint32_t sb = smem_u32(smem);
    const int tid  = threadIdx.x;
    const int wid  = tid >> 5;
    const int lane = tid & 31;
    const int bm = blockIdx.y * 128;
    const int bn = blockIdx.x * 128;
    const int p  = blockIdx.z;
    const int wm = (wid >> 1) * 32;
    const int wn = (wid & 1) * 64;

    DECL_ACCS
    Frag fr[2];

    if (tid == 0) {
#pragma unroll
        for (int s = 0; s < NSTAGE; s++) {
            MBARRIER_INIT(sb + s * 8, 1);          // full
            MBARRIER_INIT(sb + 24 + s * 8, 256);   // empty
        }
    }
    __syncthreads();

    const int CHUNKS = DIN / 64;   // 32
    auto issue = [&](int i) {
        const int s = i % NSTAGE;
        const uint32_t st = sb + STG_BASE + s * STG_BYTES;
        const uint32_t mb = sb + s * 8;
        const int k0 = i * 64;
        MBARRIER_EXPECT_TX(mb, STG_BYTES);
        TMA_2D(st + M_AH, &mUh, k0, p * GT + bm, mb);
        TMA_2D(st + M_AL, &mUl, k0, p * GT + bm, mb);
        TMA_2D(st + M_BH, &mVh, k0, p * DOUT + bn, mb);
        TMA_2D(st + M_BL, &mVl, k0, p * DOUT + bn, mb);
    };
    if (tid == 0) { issue(0); issue(1); issue(2); }

    for (int i = 0; i < CHUNKS; i++) {
        const int s = i % NSTAGE;
        MBARRIER_WAIT_PARITY(sb + s * 8, (uint32_t)((i / NSTAGE) & 1));
        mma_chunk_pipe(sb + STG_BASE + s * STG_BYTES, accf, acc1, acc2, wm, wn, lane, fr);
        MBARRIER_ARRIVE(sb + 24 + s * 8);
        if (tid == 0 && i + NSTAGE < CHUNKS) {
            MBARRIER_WAIT_PARITY(sb + 24 + s * 8, (uint32_t)((i / NSTAGE) & 1));
            issue(i + NSTAGE);
        }
    }

#pragma unroll
    for (int mf = 0; mf < 2; mf++) {
        const int row0 = bm + wm + mf * 16 + (lane >> 2);
#pragma unroll
        for (int nf = 0; nf < 8; nf++) {
            const int col = bn + wn + nf * 8 + (lane & 3) * 2;
#pragma unroll
            for (int h = 0; h < 2; h++) {
                const int row = row0 + h * 8;
                *reinterpret_cast<float2*>(
                    g_M + ((size_t)(p * GT) + row) * DOUT + col) =
                    make_float2(frag_val(accf[mf][nf], acc1[mf][nf], acc2[mf][nf], 2 * h),
                                frag_val(accf[mf][nf], acc1[mf][nf], acc2[mf][nf], 2 * h + 1));
            }
        }
    }
}

// ============================================================
// Winograd output transform + bias + relu -> E, fused rowstats
// ============================================================
__global__ void __launch_bounds__(256) wino_out_kernel(
    const float* __restrict__ bias,
    const float* __restrict__ cls_w,
    const float* __restrict__ cls_b,
    const float* __restrict__ cls_mem_w,
    float* __restrict__ E,
    float* __restrict__ p_out)
{
    const int gt = blockIdx.x;
    const int o  = threadIdx.x * 2;
    float2 m[6];
#pragma unroll
    for (int p = 0; p < 6; p++)
        m[p] = *reinterpret_cast<const float2*>(g_M + ((size_t)(p * GT) + gt) * DOUT + o);

    float ya[4], yb[4];
    ya[0] = m[0].x + m[1].x + m[2].x + m[3].x + m[4].x;
    yb[0] = m[0].y + m[1].y + m[2].y + m[3].y + m[4].y;
    ya[1] = m[1].x - m[2].x + 2.f * (m[3].x - m[4].x);
    yb[1] = m[1].y - m[2].y + 2.f * (m[3].y - m[4].y);
    ya[2] = m[1].x + m[2].x + 4.f * (m[3].x + m[4].x);
    yb[2] = m[1].y + m[2].y + 4.f * (m[3].y + m[4].y);
    ya[3] = m[1].x - m[2].x + 8.f * (m[3].x - m[4].x) + m[5].x;
    yb[3] = m[1].y - m[2].y + 8.f * (m[3].y - m[4].y) + m[5].y;

    const float2 b  = *reinterpret_cast<const float2*>(bias + o);
    const float2 w0 = *reinterpret_cast<const float2*>(cls_w + o);
    const float2 w1 = *reinterpret_cast<const float2*>(cls_mem_w + o);

    __shared__ float red[8][12];
    const int lane = threadIdx.x & 31, wrp = threadIdx.x >> 5;

    float d0[4], d1[4], qq[4];
#pragma unroll
    for (int r = 0; r < 4; r++) {
        const float v0 = fmaxf(ya[r] + b.x, 0.f);
        const float v1 = fmaxf(yb[r] + b.y, 0.f);
        const int row = 4 * gt + r;
        *reinterpret_cast<float2*>(E + (size_t)row * DOUT + o) = make_float2(v0, v1);
        uint32_t hw, lw;
        split2_f16(v0, v1, hw, lw);
        *reinterpret_cast<uint32_t*>(g_Ehi + (size_t)row * DOUT + o) = hw;
        *reinterpret_cast<uint32_t*>(g_Elo + (size_t)row * DOUT + o) = lw;
        d0[r] = v0 * w0.x + v1 * w0.y;
        d1[r] = v0 * w1.x + v1 * w1.y;
        qq[r] = v0 * v0 + v1 * v1;
    }
#pragma unroll
    for (int r = 0; r < 4; r++) {
#pragma unroll
        for (int off = 16; off; off >>= 1) {
            d0[r] += __shfl_xor_sync(0xffffffffu, d0[r], off);
            d1[r] += __shfl_xor_sync(0xffffffffu, d1[r], off);
            qq[r] += __shfl_xor_sync(0xffffffffu, qq[r], off);
        }
        if (lane == 0) {
            red[wrp][3 * r + 0] = d0[r];
            red[wrp][3 * r + 1] = d1[r];
            red[wrp][3 * r + 2] = qq[r];
        }
    }
    __syncthreads();
    if (threadIdx.x < 12) {
        float s = 0.f;
#pragma unroll
        for (int w = 0; w < 8; w++) s += red[w][threadIdx.x];
        const int r = threadIdx.x / 3, q = threadIdx.x - 3 * r;
        const int row = 4 * gt + r;
        if (q == 0)      p_out[row]   = 1.f / (1.f + __expf(-(s + cls_b[0])));
        else if (q == 1) g_w1dot[row] = s;
        else             g_qq[row]    = s;
    }
}

// ============================================================
// statically-persistent score GEMM + fused softmax partials.
// ============================================================
__global__ void __launch_bounds__(256, 1) score_mma_kernel(
    const __grid_constant__ CUtensorMap mEh,
    const __grid_constant__ CUtensorMap mEl,
    const __grid_constant__ CUtensorMap mKh,
    const __grid_constant__ CUtensorMap mKl)
{
    extern __shared__ char smem[];
    const uint32_t sb = smem_u32(smem);
    const int tid  = threadIdx.x;
    const int wid  = tid >> 5;
    const int lane = tid & 31;
    const int wm = (wid >> 1) * 32;
    const int wn = (wid & 1) * 64;
    const int bid = blockIdx.x;
    const int stride = gridDim.x;
    const int nown = (NT_S - bid + stride - 1) / stride;
    if (nown <= 0) return;
    const int total = nown * 8;

    DECL_ACCS
    Frag fr[2];

    if (tid == 0) {
#pragma unroll
        for (int s = 0; s < NSTAGE; s++) {
            MBARRIER_INIT(sb + s * 8, 1);
            MBARRIER_INIT(sb + 24 + s * 8, 256);
        }
    }
    __syncthreads();

    auto issue = [&](int gq) {
        const int tile = bid + (gq >> 3) * stride;
        const int bm = (tile >> 3) * 128;
        const int bn = (tile & 7) * 128;
        const int s = gq % NSTAGE;
        const uint32_t st = sb + STG_BASE + s * STG_BYTES;
        const uint32_t mb = sb + s * 8;
        const int k0 = (gq & 7) * 64;
        MBARRIER_EXPECT_TX(mb, STG_BYTES);
        TMA_2D(st + M_AH, &mEh, k0, bm, mb);
        TMA_2D(st + M_AL, &mEl, k0, bm, mb);
        TMA_2D(st + M_BH, &mKh, k0, bn, mb);
        TMA_2D(st + M_BL, &mKl, k0, bn, mb);
    };
    if (tid == 0) {
        issue(0);
        if (total > 1) issue(1);
        if (total > 2) issue(2);
    }

    for (int gq = 0; gq < total; gq++) {
        const int s = gq % NSTAGE;
        const uint32_t par = (uint32_t)((gq / NSTAGE) & 1);
        MBARRIER_WAIT_PARITY(sb + s * 8, par);
        mma_chunk_pipe(sb + STG_BASE + s * STG_BYTES, accf, acc1, acc2, wm, wn, lane, fr);
        MBARRIER_ARRIVE(sb + 24 + s * 8);
        if (tid == 0 && gq + NSTAGE < total) {
            MBARRIER_WAIT_PARITY(sb + 24 + s * 8, par);
            issue(gq + NSTAGE);
        }
        if ((gq & 7) == 7) {
            const int tile = bid + (gq >> 3) * stride;
            const int bm = (tile >> 3) * 128;
            const int bn = (tile & 7) * 128;
            const int nblk = (bn + wn) >> 6;
#pragma unroll
            for (int mf = 0; mf < 2; mf++) {
#pragma unroll
                for (int h = 0; h < 2; h++) {
                    const int row = bm + wm + mf * 16 + (lane >> 2) + h * 8;
                    float vals[16];
                    float mt = -INFINITY, bv = -INFINITY;
                    int bi = 0;
#pragma unroll
                    for (int nf = 0; nf < 8; nf++) {
                        const int col0 = bn + wn + nf * 8 + (lane & 3) * 2;
                        const float v0 = frag_val(accf[mf][nf], acc1[mf][nf], acc2[mf][nf], 2 * h);
                        const float v1 = frag_val(accf[mf][nf], acc1[mf][nf], acc2[mf][nf], 2 * h + 1);
                        vals[2 * nf] = v0; vals[2 * nf + 1] = v1;
                        if (v0 > bv || (v0 == bv && col0 < bi)) { bv = v0; bi = col0; }
                        if (v1 > bv || (v1 == bv && col0 + 1 < bi)) { bv = v1; bi = col0 + 1; }
                        mt = fmaxf(mt, fmaxf(v0, v1));
                    }
                    float lt = 0.f, dt = 0.f;
#pragma unroll
                    for (int nf = 0; nf < 8; nf++) {
                        const int col0 = bn + wn + nf * 8 + (lane & 3) * 2;
                        const float e0 = __expf(vals[2 * nf] - mt);
                        const float e1 = __expf(vals[2 * nf + 1] - mt);
                        lt += e0 + e1;
                        dt += e0 * __ldg(&g_kv[col0]) + e1 * __ldg(&g_kv[col0 + 1]);
                    }
#pragma unroll
                    for (int off = 1; off < 4; off <<= 1) {
                        const float mo  = __shfl_xor_sync(0xffffffffu, mt, off);
                        const float lo  = __shfl_xor_sync(0xffffffffu, lt, off);
                        const float dto = __shfl_xor_sync(0xffffffffu, dt, off);
                        const float bvo = __shfl_xor_sync(0xffffffffu, bv, off);
                        const int   bio = __shfl_xor_sync(0xffffffffu, bi, off);
                        const float M  = fmaxf(mt, mo);
                        const float s1 = __expf(mt - M);
                        const float s2 = __expf(mo - M);
                        lt = lt * s1 + lo * s2;
                        dt = dt * s1 + dto * s2;
                        mt = M;
                        if (bvo > bv || (bvo == bv && bio < bi)) { bv = bvo; bi = bio; }
                    }
                    if ((lane & 3) == 0) {
                        const size_t off = (size_t)row * 16 + nblk;
                        g_pm[off]  = make_float4(mt, lt, dt, bv);
                        g_pbi[off] = bi;
                    }
                }
            }
            RESET_ACCS
        }
    }
}

// ============================================================
// final: merge 16 per-row partials -> up_score + both losses
// ============================================================
__global__ void softmax_final_kernel(const float* __restrict__ cls_mem_b,
                                     float* __restrict__ up_out,
                                     float* __restrict__ nor_out,
                                     float* __restrict__ abn_out)
{
    const int row = blockIdx.x * 256 + threadIdx.x;
    float m = -INFINITY, l = 0.f, d = 0.f;
    float bv0 = -INFINITY, bv1 = -INFINITY;
    int bi0 = 0, bi1 = 0;
#pragma unroll
    for (int b = 0; b < 16; b++) {
        const float4 p = g_pm[(size_t)row * 16 + b];
        const int  pbi = g_pbi[(size_t)row * 16 + b];
        const float M  = fmaxf(m, p.x);
        const float s1 = __expf(m - M);
        const float s2 = __expf(p.x - M);
        l = l * s1 + p.y * s2;
        d = d * s1 + p.z * s2;
        m = M;
        if (b < 8) { if (p.w > bv0 || (p.w == bv0 && pbi < bi0)) { bv0 = p.w; bi0 = pbi; } }
        else       { if (p.w > bv1 || (p.w == bv1 && pbi < bi1)) { bv1 = p.w; bi1 = pbi; } }
    }
    const float x = g_w1dot[row] + d / l + cls_mem_b[0];
    up_out[row] = 1.f / (1.f + __expf(-x));
    const float qq = g_qq[row];
    nor_out[row] = (qq - 2.f * bv0 + g_kkn[bi0]) * (1.f / 512.f);
    abn_out[row] = (qq - 2.f * bv1 + g_kkn[bi1]) * (1.f / 512.f);
}

// ============================================================
// host: tensormap construction (driver entry point via cudart; no -lcuda)
// ============================================================
typedef CUresult (*PFN_tmEnc)(CUtensorMap*, CUtensorMapDataType, cuuint32_t, void*,
                              const cuuint64_t*, const cuuint64_t*, const cuuint32_t*,
                              const cuuint32_t*, CUtensorMapInterleave, CUtensorMapSwizzle,
                              CUtensorMapL2promotion, CUtensorMapFloatOOBfill);

static void enc2d(PFN_tmEnc f, CUtensorMap* m, void* addr,
                  unsigned long long d0, unsigned long long d1,
                  unsigned long long stride_bytes)
{
    cuuint64_t dims[2]    = {(cuuint64_t)d0, (cuuint64_t)d1};
    cuuint64_t strides[1] = {(cuuint64_t)stride_bytes};
    cuuint32_t box[2]     = {64u, 128u};
    cuuint32_t es[2]      = {1u, 1u};
    f(m, CU_TENSOR_MAP_DATA_TYPE_FLOAT16, 2, addr, dims, strides, box, es,
      CU_TENSOR_MAP_INTERLEAVE_NONE, CU_TENSOR_MAP_SWIZZLE_128B,
      CU_TENSOR_MAP_L2_PROMOTION_L2_128B, CU_TENSOR_MAP_FLOAT_OOB_FILL_NONE);
}

extern "C" void kernel_launch(void* const* d_in, const int* in_sizes, int n_in,
                              void* d_out, int out_size)
{
    const float* ref_nor   = (const float*)d_in[0];
    // d_in[1] = ref_abn : dead (only feeds the discarded p_score[B:])
    const float* nor_keys  = (const float*)d_in[2];
    const float* abn_keys  = (const float*)d_in[3];
    const float* conv_w    = (const float*)d_in[4];
    const float* conv_b    = (const float*)d_in[5];
    const float* cls_w     = (const float*)d_in[6];
    const float* cls_b     = (const float*)d_in[7];
    const float* cls_mem_w = (const float*)d_in[8];
    const float* cls_mem_b = (const float*)d_in[9];

    float* out      = (float*)d_out;
    float* p_score  = out;
    float* up_score = out + ROWS;
    float* nor_loss = out + 2 * ROWS;
    float* abn_loss = out + 3 * ROWS;
    float* E        = out + 4 * ROWS;

    PFN_tmEnc enc = nullptr;
    cudaDriverEntryPointQueryResult qr;
    cudaGetDriverEntryPoint("cuTensorMapEncodeTiled", (void**)&enc,
                            cudaEnableDefault, &qr);
    void *pUh, *pUl, *pVh, *pVl, *pEh, *pEl, *pKh, *pKl;
    cudaGetSymbolAddress(&pUh, g_Uhi); cudaGetSymbolAddress(&pUl, g_Ulo);
    cudaGetSymbolAddress(&pVh, g_Vhi); cudaGetSymbolAddress(&pVl, g_Vlo);
    cudaGetSymbolAddress(&pEh, g_Ehi); cudaGetSymbolAddress(&pEl, g_Elo);
    cudaGetSymbolAddress(&pKh, g_Khi); cudaGetSymbolAddress(&pKl, g_Klo);

    CUtensorMap mUh, mUl, mVh, mVl, mEh, mEl, mKh, mKl;
    enc2d(enc, &mUh, pUh, DIN,  NPTS * GT,   (unsigned long long)DIN  * 2);
    enc2d(enc, &mUl, pUl, DIN,  NPTS * GT,   (unsigned long long)DIN  * 2);
    enc2d(enc, &mVh, pVh, DIN,  NPTS * DOUT, (unsigned long long)DIN  * 2);
    enc2d(enc, &mVl, pVl, DIN,  NPTS * DOUT, (unsigned long long)DIN  * 2);
    enc2d(enc, &mEh, pEh, DOUT, ROWS,        (unsigned long long)DOUT * 2);
    enc2d(enc, &mEl, pEl, DOUT, ROWS,        (unsigned long long)DOUT * 2);
    enc2d(enc, &mKh, pKh, DOUT, NKEYS,       (unsigned long long)DOUT * 2);
    enc2d(enc, &mKl, pKl, DOUT, NKEYS,       (unsigned long long)DOUT * 2);

    int nsm = 148;
    cudaDeviceGetAttribute(&nsm, cudaDevAttrMultiProcessorCount, 0);

    cudaFuncSetAttribute(wino_gemm_kernel,  cudaFuncAttributeMaxDynamicSharedMemorySize, SMEM_BYTES);
    cudaFuncSetAttribute(score_mma_kernel, cudaFuncAttributeMaxDynamicSharedMemorySize, SMEM_BYTES);

    prep_kernel<<<GT + 2048 + 128, 256>>>(ref_nor, conv_w, nor_keys, abn_keys, cls_mem_w);

    wino_gemm_kernel<<<dim3(4, 16, 6), 256, SMEM_BYTES>>>(mUh, mUl, mVh, mVl);
    wino_out_kernel<<<GT, 256>>>(conv_b, cls_w, cls_b, cls_mem_w, E, p_score);
    score_mma_kernel<<<nsm, 256, SMEM_BYTES>>>(mEh, mEl, mKh, mKl);
    softmax_final_kernel<<<32, 256>>>(cls_mem_b, up_score, nor_loss, abn_loss);
}